// round 1
// baseline (speedup 1.0000x reference)
#include <cuda_runtime.h>
#include <cuda_bf16.h>
#include <cstdint>

// Problem constants
#define BB 4
#define SS 2048
#define DD 1024
#define HH 16
#define DKK 64
#define MTOT (BB*SS)          // 8192

// Head-major scratch [B*H, S, DK] for Q,K,V projections (32 MB each)
__device__ float g_Q[(size_t)MTOT * DD];
__device__ float g_K[(size_t)MTOT * DD];
__device__ float g_V[(size_t)MTOT * DD];

// ---------------------------------------------------------------------------
// Fused QKV projection: Y = X @ W^T + b, scattered to [B,H,S,DK] layout.
// blockIdx.z selects (q,Wq,bq)->g_Q, (k,Wk,bk)->g_K, (v,Wv,bv)->g_V.
// Tile 64x64, K-chunk 16, 256 threads, 4x4 microtile per thread.
// ---------------------------------------------------------------------------
__global__ void qkv_gemm(const float* __restrict__ q,
                         const float* __restrict__ k,
                         const float* __restrict__ v,
                         const float* __restrict__ Wq, const float* __restrict__ bq,
                         const float* __restrict__ Wk, const float* __restrict__ bk,
                         const float* __restrict__ Wv, const float* __restrict__ bv)
{
    __shared__ float Xs[16][65];   // [kk][m], pad avoids write conflicts
    __shared__ float Ws[16][65];   // [kk][n]

    const float* X; const float* W; const float* bias; float* out;
    int z = blockIdx.z;
    if (z == 0)      { X = q; W = Wq; bias = bq; out = g_Q; }
    else if (z == 1) { X = k; W = Wk; bias = bk; out = g_K; }
    else             { X = v; W = Wv; bias = bv; out = g_V; }

    const int m0 = blockIdx.x * 64;
    const int n0 = blockIdx.y * 64;
    const int tid = threadIdx.x;
    const int tx = tid & 15;       // 0..15 -> n microcols (stride 16)
    const int ty = tid >> 4;       // 0..15 -> m microrows (x4)

    float acc[4][4];
#pragma unroll
    for (int i = 0; i < 4; i++)
#pragma unroll
        for (int j = 0; j < 4; j++) acc[i][j] = 0.f;

    for (int kc = 0; kc < DD; kc += 16) {
        // load 64x16 tiles of X and W (K-contiguous rows -> coalesced)
#pragma unroll
        for (int e = tid; e < 1024; e += 256) {
            int r = e >> 4;        // row in tile (m or n)
            int c = e & 15;        // k within chunk
            Xs[c][r] = X[(size_t)(m0 + r) * DD + kc + c];
            Ws[c][r] = W[(size_t)(n0 + r) * DD + kc + c];
        }
        __syncthreads();
#pragma unroll
        for (int kk = 0; kk < 16; kk++) {
            float a[4], bw[4];
#pragma unroll
            for (int i = 0; i < 4; i++) a[i] = Xs[kk][4 * ty + i];
#pragma unroll
            for (int j = 0; j < 4; j++) bw[j] = Ws[kk][tx + 16 * j];
#pragma unroll
            for (int i = 0; i < 4; i++)
#pragma unroll
                for (int j = 0; j < 4; j++) acc[i][j] += a[i] * bw[j];
        }
        __syncthreads();
    }

    // epilogue: add bias, scatter to head-major [B*H, S, DK]
#pragma unroll
    for (int i = 0; i < 4; i++) {
        int m = m0 + 4 * ty + i;
        int b = m >> 11;           // / 2048
        int s = m & 2047;
#pragma unroll
        for (int j = 0; j < 4; j++) {
            int n = n0 + tx + 16 * j;
            int h = n >> 6;
            int d = n & 63;
            out[(((size_t)(b * HH + h) * SS) + s) * DKK + d] = acc[i][j] + bias[n];
        }
    }
}

// ---------------------------------------------------------------------------
// Causal flash attention, fp32. BM=BN=64, DK=64, 256 threads.
// Thread (ty,tx): rows 4*ty+i, cols/dims tx+16*j (conflict-free smem reads).
// Online softmax state per thread-row, replicated across 16-lane row group.
// Only KV tiles <= diagonal are visited; only the diagonal tile is masked.
// ---------------------------------------------------------------------------
__global__ void flash_attn(float* __restrict__ out)
{
    extern __shared__ float sm[];
    float* Qs = sm;                 // 64*65
    float* Ks = sm + 64 * 65;       // 64*65
    float* Vs = sm + 2 * 64 * 65;   // 64*65
    float* Ps = sm + 3 * 64 * 65;   // 64*65

    const int bh = blockIdx.y;      // b*H + h
    const int qt = blockIdx.x;      // query tile
    const int m0 = qt * 64;

    const float* Qp = g_Q + (size_t)bh * SS * DKK;
    const float* Kp = g_K + (size_t)bh * SS * DKK;
    const float* Vp = g_V + (size_t)bh * SS * DKK;

    const int tid = threadIdx.x;
    const int tx = tid & 15;
    const int ty = tid >> 4;

    // load Q tile
#pragma unroll
    for (int e = tid; e < 4096; e += 256) {
        int r = e >> 6, c = e & 63;
        Qs[r * 65 + c] = Qp[(size_t)(m0 + r) * DKK + c];
    }

    float m_i[4], l_i[4], acc[4][4];
#pragma unroll
    for (int i = 0; i < 4; i++) {
        m_i[i] = -1e30f; l_i[i] = 0.f;
#pragma unroll
        for (int j = 0; j < 4; j++) acc[i][j] = 0.f;
    }
    __syncthreads();

    const float scale = 0.125f;     // 1/sqrt(64)

    for (int t = 0; t <= qt; t++) {
        const int n0 = t * 64;
        // load K, V tiles
#pragma unroll
        for (int e = tid; e < 4096; e += 256) {
            int r = e >> 6, c = e & 63;
            Ks[r * 65 + c] = Kp[(size_t)(n0 + r) * DKK + c];
            Vs[r * 65 + c] = Vp[(size_t)(n0 + r) * DKK + c];
        }
        __syncthreads();

        // scores S = Q K^T
        float s[4][4];
#pragma unroll
        for (int i = 0; i < 4; i++)
#pragma unroll
            for (int j = 0; j < 4; j++) s[i][j] = 0.f;

#pragma unroll 4
        for (int kk = 0; kk < 64; kk++) {
            float a[4], bk_[4];
#pragma unroll
            for (int i = 0; i < 4; i++) a[i] = Qs[(4 * ty + i) * 65 + kk];
#pragma unroll
            for (int j = 0; j < 4; j++) bk_[j] = Ks[(tx + 16 * j) * 65 + kk];
#pragma unroll
            for (int i = 0; i < 4; i++)
#pragma unroll
                for (int j = 0; j < 4; j++) s[i][j] += a[i] * bk_[j];
        }

        const bool diag = (t == qt);
#pragma unroll
        for (int i = 0; i < 4; i++) {
            const int qrow = m0 + 4 * ty + i;
            float rmax = -1e30f;
#pragma unroll
            for (int j = 0; j < 4; j++) {
                float sv = s[i][j] * scale;
                int kcol = n0 + tx + 16 * j;
                if (diag && kcol > qrow) sv = -1e30f;
                s[i][j] = sv;
                rmax = fmaxf(rmax, sv);
            }
#pragma unroll
            for (int off = 8; off; off >>= 1)
                rmax = fmaxf(rmax, __shfl_xor_sync(0xffffffffu, rmax, off));
            float mnew = fmaxf(m_i[i], rmax);
            float corr = __expf(m_i[i] - mnew);
            float rsum = 0.f;
#pragma unroll
            for (int j = 0; j < 4; j++) {
                float p = __expf(s[i][j] - mnew);
                s[i][j] = p;
                rsum += p;
            }
#pragma unroll
            for (int off = 8; off; off >>= 1)
                rsum += __shfl_xor_sync(0xffffffffu, rsum, off);
            l_i[i] = l_i[i] * corr + rsum;
            m_i[i] = mnew;
#pragma unroll
            for (int j = 0; j < 4; j++) acc[i][j] *= corr;
            // stage P tile
#pragma unroll
            for (int j = 0; j < 4; j++)
                Ps[(4 * ty + i) * 65 + tx + 16 * j] = s[i][j];
        }
        __syncthreads();

        // O += P V
#pragma unroll 4
        for (int jj = 0; jj < 64; jj++) {
            float pv[4], vv[4];
#pragma unroll
            for (int i = 0; i < 4; i++) pv[i] = Ps[(4 * ty + i) * 65 + jj];
#pragma unroll
            for (int j = 0; j < 4; j++) vv[j] = Vs[jj * 65 + tx + 16 * j];
#pragma unroll
            for (int i = 0; i < 4; i++)
#pragma unroll
                for (int j = 0; j < 4; j++) acc[i][j] += pv[i] * vv[j];
        }
        __syncthreads();
    }

    // epilogue: normalize, write [B,S,D] with D = h*64 + d
    const int b = bh >> 4;
    const int h = bh & 15;
#pragma unroll
    for (int i = 0; i < 4; i++) {
        int srow = m0 + 4 * ty + i;
        float inv = 1.0f / l_i[i];
#pragma unroll
        for (int j = 0; j < 4; j++) {
            int d = tx + 16 * j;
            out[((size_t)(b * SS + srow)) * DD + h * DKK + d] = acc[i][j] * inv;
        }
    }
}

// ---------------------------------------------------------------------------
extern "C" void kernel_launch(void* const* d_in, const int* in_sizes, int n_in,
                              void* d_out, int out_size)
{
    const float* q  = (const float*)d_in[0];
    const float* v  = (const float*)d_in[1];
    const float* k  = (const float*)d_in[2];
    // d_in[3] = attn_mask (bool causal) — known analytically, unused
    const float* Wq = (const float*)d_in[4];
    const float* bq = (const float*)d_in[5];
    const float* Wk = (const float*)d_in[6];
    const float* bk = (const float*)d_in[7];
    const float* Wv = (const float*)d_in[8];
    const float* bv = (const float*)d_in[9];
    float* out = (float*)d_out;

    dim3 gGemm(MTOT / 64, DD / 64, 3);     // 128 x 16 x 3
    qkv_gemm<<<gGemm, 256>>>(q, k, v, Wq, bq, Wk, bk, Wv, bv);

    const int smemBytes = 4 * 64 * 65 * sizeof(float);   // 66560
    cudaFuncSetAttribute(flash_attn, cudaFuncAttributeMaxDynamicSharedMemorySize, smemBytes);
    dim3 gAttn(SS / 64, BB * HH);          // 32 x 64
    flash_attn<<<gAttn, 256, smemBytes>>>(out);
}

// round 2
// speedup vs baseline: 1.8268x; 1.8268x over previous
#include <cuda_runtime.h>
#include <cuda_bf16.h>
#include <cstdint>

#define BB 4
#define SS 2048
#define DD 1024
#define HH 16
#define DKK 64
#define MTOT (BB*SS)          // 8192

// Head-major scratch [B*H, S, DK]
__device__ float g_Q[(size_t)MTOT * DD];
__device__ float g_K[(size_t)MTOT * DD];
__device__ float g_V[(size_t)MTOT * DD];

__device__ __forceinline__ uint32_t f2tf32(float f) {
    uint32_t u;
    asm("cvt.rna.tf32.f32 %0, %1;" : "=r"(u) : "f"(f));
    return u;
}

#define MMA_TF32(d, a, b)                                                     \
    asm volatile("mma.sync.aligned.m16n8k8.row.col.f32.tf32.tf32.f32 "        \
                 "{%0,%1,%2,%3}, {%4,%5,%6,%7}, {%8,%9}, {%0,%1,%2,%3};"      \
                 : "+f"(d[0]), "+f"(d[1]), "+f"(d[2]), "+f"(d[3])             \
                 : "r"(a[0]), "r"(a[1]), "r"(a[2]), "r"(a[3]),                \
                   "r"(b[0]), "r"(b[1]));

// ---------------------------------------------------------------------------
// QKV projection with tf32 tensor cores: Y = X @ W^T + b -> head-major scratch
// Block tile 128x128, 8 warps (2m x 4n), warp tile 64x32, K chunk 32.
// SMEM layout [row][k] stride 36 floats: bank = (4*row + k) % 32 -> conflict-
// free for both STS.128 fills and m16n8k8 fragment reads.
// ---------------------------------------------------------------------------
__global__ __launch_bounds__(256, 2)
void qkv_gemm_tf32(const float* __restrict__ q,
                   const float* __restrict__ k,
                   const float* __restrict__ v,
                   const float* __restrict__ Wq, const float* __restrict__ bq,
                   const float* __restrict__ Wk, const float* __restrict__ bk,
                   const float* __restrict__ Wv, const float* __restrict__ bv)
{
    __shared__ uint32_t Xs[128 * 36];
    __shared__ uint32_t Ws[128 * 36];

    const float* X; const float* W; const float* bias; float* out;
    int z = blockIdx.z;
    if (z == 0)      { X = q; W = Wq; bias = bq; out = g_Q; }
    else if (z == 1) { X = k; W = Wk; bias = bk; out = g_K; }
    else             { X = v; W = Wv; bias = bv; out = g_V; }

    const int m0 = blockIdx.x * 128;
    const int n0 = blockIdx.y * 128;
    const int tid  = threadIdx.x;
    const int warp = tid >> 5;
    const int lane = tid & 31;
    const int wm = warp >> 2;       // 0..1 -> 64 rows
    const int wn = warp & 3;        // 0..3 -> 32 cols
    const int lr = lane >> 2;       // 0..7
    const int lc = lane & 3;        // 0..3

    float acc[4][4][4];
#pragma unroll
    for (int mi = 0; mi < 4; mi++)
#pragma unroll
        for (int ni = 0; ni < 4; ni++)
#pragma unroll
            for (int c = 0; c < 4; c++) acc[mi][ni][c] = 0.f;

    for (int kc = 0; kc < DD; kc += 32) {
        // fill: 128 rows x 32 k (float4 per thread slot), convert to tf32
#pragma unroll
        for (int e = tid; e < 1024; e += 256) {
            int r  = e >> 3;
            int cq = e & 7;
            float4 xv = *(const float4*)&X[(size_t)(m0 + r) * DD + kc + cq * 4];
            float4 wv = *(const float4*)&W[(size_t)(n0 + r) * DD + kc + cq * 4];
            uint4 xt, wt;
            xt.x = f2tf32(xv.x); xt.y = f2tf32(xv.y);
            xt.z = f2tf32(xv.z); xt.w = f2tf32(xv.w);
            wt.x = f2tf32(wv.x); wt.y = f2tf32(wv.y);
            wt.z = f2tf32(wv.z); wt.w = f2tf32(wv.w);
            *(uint4*)&Xs[r * 36 + cq * 4] = xt;
            *(uint4*)&Ws[r * 36 + cq * 4] = wt;
        }
        __syncthreads();

#pragma unroll
        for (int ks = 0; ks < 4; ks++) {
            const int k0 = ks * 8;
            uint32_t a[4][4];
#pragma unroll
            for (int mi = 0; mi < 4; mi++) {
                int row = wm * 64 + mi * 16 + lr;
                a[mi][0] = Xs[row * 36 + k0 + lc];
                a[mi][1] = Xs[(row + 8) * 36 + k0 + lc];
                a[mi][2] = Xs[row * 36 + k0 + lc + 4];
                a[mi][3] = Xs[(row + 8) * 36 + k0 + lc + 4];
            }
            uint32_t b[4][2];
#pragma unroll
            for (int ni = 0; ni < 4; ni++) {
                int col = wn * 32 + ni * 8 + lr;
                b[ni][0] = Ws[col * 36 + k0 + lc];
                b[ni][1] = Ws[col * 36 + k0 + lc + 4];
            }
#pragma unroll
            for (int mi = 0; mi < 4; mi++)
#pragma unroll
                for (int ni = 0; ni < 4; ni++)
                    MMA_TF32(acc[mi][ni], a[mi], b[ni]);
        }
        __syncthreads();
    }

    // epilogue: bias + scatter to head-major [B*H, S, DK], float2 stores
#pragma unroll
    for (int mi = 0; mi < 4; mi++) {
#pragma unroll
        for (int ni = 0; ni < 4; ni++) {
            int m = m0 + wm * 64 + mi * 16 + lr;
            int n = n0 + wn * 32 + ni * 8 + 2 * lc;
            float b0 = __ldg(&bias[n]), b1 = __ldg(&bias[n + 1]);
            int h = n >> 6, d = n & 63;
#pragma unroll
            for (int half = 0; half < 2; half++) {
                int mm = m + half * 8;
                int b_ = mm >> 11, s = mm & 2047;
                float2 val;
                val.x = acc[mi][ni][half * 2 + 0] + b0;
                val.y = acc[mi][ni][half * 2 + 1] + b1;
                *(float2*)&out[(((size_t)(b_ * HH + h) * SS) + s) * DKK + d] = val;
            }
        }
    }
}

// ---------------------------------------------------------------------------
// Causal flash attention, fp32 SIMT. BM=128, BN=64, DK=64, 256 threads.
// Microtile 8 rows x 4 cols per thread: 12 LDS per 32 FMA (vs 8/16 before).
// ---------------------------------------------------------------------------
__global__ __launch_bounds__(256, 1)
void flash_attn(float* __restrict__ out)
{
    extern __shared__ float sm[];
    float* Qs = sm;                       // 128*65
    float* Ks = Qs + 128 * 65;            // 64*65
    float* Vs = Ks + 64 * 65;             // 64*65
    float* Ps = Vs + 64 * 65;             // 128*66

    const int bh = blockIdx.y;
    const int qt = blockIdx.x;
    const int m0 = qt * 128;

    const float* Qp = g_Q + (size_t)bh * SS * DKK;
    const float* Kp = g_K + (size_t)bh * SS * DKK;
    const float* Vp = g_V + (size_t)bh * SS * DKK;

    const int tid = threadIdx.x;
    const int tx = tid & 15;
    const int ty = tid >> 4;

    // load Q tile (128x64)
#pragma unroll
    for (int e = tid; e < 2048; e += 256) {
        int r = e >> 4, c4 = e & 15;
        float4 qv = *(const float4*)&Qp[(size_t)(m0 + r) * DKK + c4 * 4];
        Qs[r * 65 + c4 * 4 + 0] = qv.x;
        Qs[r * 65 + c4 * 4 + 1] = qv.y;
        Qs[r * 65 + c4 * 4 + 2] = qv.z;
        Qs[r * 65 + c4 * 4 + 3] = qv.w;
    }

    float m_i[8], l_i[8], acc[8][4];
#pragma unroll
    for (int i = 0; i < 8; i++) {
        m_i[i] = -1e30f; l_i[i] = 0.f;
#pragma unroll
        for (int j = 0; j < 4; j++) acc[i][j] = 0.f;
    }
    __syncthreads();

    const float scale = 0.125f;      // 1/sqrt(64)
    const int ntiles = 2 * qt + 2;   // KV tiles of 64 covering rows

    for (int t = 0; t < ntiles; t++) {
        const int n0 = t * 64;
#pragma unroll
        for (int e = tid; e < 1024; e += 256) {
            int r = e >> 4, c4 = e & 15;
            float4 kv = *(const float4*)&Kp[(size_t)(n0 + r) * DKK + c4 * 4];
            float4 vv = *(const float4*)&Vp[(size_t)(n0 + r) * DKK + c4 * 4];
            Ks[r * 65 + c4 * 4 + 0] = kv.x;
            Ks[r * 65 + c4 * 4 + 1] = kv.y;
            Ks[r * 65 + c4 * 4 + 2] = kv.z;
            Ks[r * 65 + c4 * 4 + 3] = kv.w;
            Vs[r * 65 + c4 * 4 + 0] = vv.x;
            Vs[r * 65 + c4 * 4 + 1] = vv.y;
            Vs[r * 65 + c4 * 4 + 2] = vv.z;
            Vs[r * 65 + c4 * 4 + 3] = vv.w;
        }
        __syncthreads();

        float s[8][4];
#pragma unroll
        for (int i = 0; i < 8; i++)
#pragma unroll
            for (int j = 0; j < 4; j++) s[i][j] = 0.f;

#pragma unroll 4
        for (int kk = 0; kk < 64; kk++) {
            float a[8], bk_[4];
#pragma unroll
            for (int i = 0; i < 8; i++) a[i] = Qs[(8 * ty + i) * 65 + kk];
#pragma unroll
            for (int j = 0; j < 4; j++) bk_[j] = Ks[(tx + 16 * j) * 65 + kk];
#pragma unroll
            for (int i = 0; i < 8; i++)
#pragma unroll
                for (int j = 0; j < 4; j++) s[i][j] += a[i] * bk_[j];
        }

        const bool need_mask = (t >= 2 * qt);
#pragma unroll
        for (int i = 0; i < 8; i++) {
            const int qrow = m0 + 8 * ty + i;
            float rmax = -1e30f;
#pragma unroll
            for (int j = 0; j < 4; j++) {
                float sv = s[i][j] * scale;
                int kcol = n0 + tx + 16 * j;
                if (need_mask && kcol > qrow) sv = -1e30f;
                s[i][j] = sv;
                rmax = fmaxf(rmax, sv);
            }
#pragma unroll
            for (int off = 8; off; off >>= 1)
                rmax = fmaxf(rmax, __shfl_xor_sync(0xffffffffu, rmax, off));
            float mnew = fmaxf(m_i[i], rmax);
            float corr = __expf(m_i[i] - mnew);
            float rsum = 0.f;
#pragma unroll
            for (int j = 0; j < 4; j++) {
                float p = __expf(s[i][j] - mnew);
                s[i][j] = p;
                rsum += p;
            }
#pragma unroll
            for (int off = 8; off; off >>= 1)
                rsum += __shfl_xor_sync(0xffffffffu, rsum, off);
            l_i[i] = l_i[i] * corr + rsum;
            m_i[i] = mnew;
#pragma unroll
            for (int j = 0; j < 4; j++) acc[i][j] *= corr;
#pragma unroll
            for (int j = 0; j < 4; j++)
                Ps[(8 * ty + i) * 66 + tx + 16 * j] = s[i][j];
        }
        __syncthreads();

#pragma unroll 4
        for (int jj = 0; jj < 64; jj++) {
            float pv[8], vv[4];
#pragma unroll
            for (int i = 0; i < 8; i++) pv[i] = Ps[(8 * ty + i) * 66 + jj];
#pragma unroll
            for (int j = 0; j < 4; j++) vv[j] = Vs[jj * 65 + tx + 16 * j];
#pragma unroll
            for (int i = 0; i < 8; i++)
#pragma unroll
                for (int j = 0; j < 4; j++) acc[i][j] += pv[i] * vv[j];
        }
        __syncthreads();
    }

    const int b = bh >> 4;
    const int h = bh & 15;
#pragma unroll
    for (int i = 0; i < 8; i++) {
        int srow = m0 + 8 * ty + i;
        float inv = 1.0f / l_i[i];
#pragma unroll
        for (int j = 0; j < 4; j++) {
            int d = tx + 16 * j;
            out[((size_t)(b * SS + srow)) * DD + h * DKK + d] = acc[i][j] * inv;
        }
    }
}

// ---------------------------------------------------------------------------
extern "C" void kernel_launch(void* const* d_in, const int* in_sizes, int n_in,
                              void* d_out, int out_size)
{
    const float* q  = (const float*)d_in[0];
    const float* v  = (const float*)d_in[1];
    const float* k  = (const float*)d_in[2];
    // d_in[3] = attn_mask (causal, known analytically) — unused
    const float* Wq = (const float*)d_in[4];
    const float* bq = (const float*)d_in[5];
    const float* Wk = (const float*)d_in[6];
    const float* bk = (const float*)d_in[7];
    const float* Wv = (const float*)d_in[8];
    const float* bv = (const float*)d_in[9];
    float* out = (float*)d_out;

    dim3 gGemm(MTOT / 128, DD / 128, 3);   // 64 x 8 x 3
    qkv_gemm_tf32<<<gGemm, 256>>>(q, k, v, Wq, bq, Wk, bk, Wv, bv);

    const int smemBytes = (128 * 65 + 64 * 65 + 64 * 65 + 128 * 66) * sizeof(float);
    cudaFuncSetAttribute(flash_attn, cudaFuncAttributeMaxDynamicSharedMemorySize, smemBytes);
    dim3 gAttn(SS / 128, BB * HH);         // 16 x 64
    flash_attn<<<gAttn, 256, smemBytes>>>(out);
}

// round 3
// speedup vs baseline: 3.5390x; 1.9373x over previous
#include <cuda_runtime.h>
#include <cuda_bf16.h>
#include <cstdint>

#define BB 4
#define SS 2048
#define DD 1024
#define HH 16
#define DKK 64
#define MTOT (BB*SS)          // 8192

// log2(e) / sqrt(64) folded into Q projection
#define QSCALE 0.18033688011112042f

// Head-major scratch [B*H, S, DK]
__device__ float g_Q[(size_t)MTOT * DD];
__device__ float g_K[(size_t)MTOT * DD];
__device__ float g_V[(size_t)MTOT * DD];

__device__ __forceinline__ uint32_t f2tf32(float f) {
    uint32_t u;
    asm("cvt.rna.tf32.f32 %0, %1;" : "=r"(u) : "f"(f));
    return u;
}
__device__ __forceinline__ float ex2(float x) {
    float y;
    asm("ex2.approx.ftz.f32 %0, %1;" : "=f"(y) : "f"(x));
    return y;
}

#define MMA_TF32(d, a, b)                                                     \
    asm volatile("mma.sync.aligned.m16n8k8.row.col.f32.tf32.tf32.f32 "        \
                 "{%0,%1,%2,%3}, {%4,%5,%6,%7}, {%8,%9}, {%0,%1,%2,%3};"      \
                 : "+f"(d[0]), "+f"(d[1]), "+f"(d[2]), "+f"(d[3])             \
                 : "r"(a[0]), "r"(a[1]), "r"(a[2]), "r"(a[3]),                \
                   "r"(b[0]), "r"(b[1]));

// ---------------------------------------------------------------------------
// QKV projection, tf32 tensor cores. Y = X @ W^T + b -> head-major scratch.
// Q output additionally scaled by QSCALE (softmax scale folded in).
// ---------------------------------------------------------------------------
__global__ __launch_bounds__(256, 2)
void qkv_gemm_tf32(const float* __restrict__ q,
                   const float* __restrict__ k,
                   const float* __restrict__ v,
                   const float* __restrict__ Wq, const float* __restrict__ bq,
                   const float* __restrict__ Wk, const float* __restrict__ bk,
                   const float* __restrict__ Wv, const float* __restrict__ bv)
{
    __shared__ uint32_t Xs[128 * 36];
    __shared__ uint32_t Ws[128 * 36];

    const float* X; const float* W; const float* bias; float* out;
    int z = blockIdx.z;
    float oscale;
    if (z == 0)      { X = q; W = Wq; bias = bq; out = g_Q; oscale = QSCALE; }
    else if (z == 1) { X = k; W = Wk; bias = bk; out = g_K; oscale = 1.f; }
    else             { X = v; W = Wv; bias = bv; out = g_V; oscale = 1.f; }

    const int m0 = blockIdx.x * 128;
    const int n0 = blockIdx.y * 128;
    const int tid  = threadIdx.x;
    const int warp = tid >> 5;
    const int lane = tid & 31;
    const int wm = warp >> 2;
    const int wn = warp & 3;
    const int lr = lane >> 2;
    const int lc = lane & 3;

    float acc[4][4][4];
#pragma unroll
    for (int mi = 0; mi < 4; mi++)
#pragma unroll
        for (int ni = 0; ni < 4; ni++)
#pragma unroll
            for (int c = 0; c < 4; c++) acc[mi][ni][c] = 0.f;

    for (int kc = 0; kc < DD; kc += 32) {
#pragma unroll
        for (int e = tid; e < 1024; e += 256) {
            int r  = e >> 3;
            int cq = e & 7;
            float4 xv = *(const float4*)&X[(size_t)(m0 + r) * DD + kc + cq * 4];
            float4 wv = *(const float4*)&W[(size_t)(n0 + r) * DD + kc + cq * 4];
            uint4 xt, wt;
            xt.x = f2tf32(xv.x); xt.y = f2tf32(xv.y);
            xt.z = f2tf32(xv.z); xt.w = f2tf32(xv.w);
            wt.x = f2tf32(wv.x); wt.y = f2tf32(wv.y);
            wt.z = f2tf32(wv.z); wt.w = f2tf32(wv.w);
            *(uint4*)&Xs[r * 36 + cq * 4] = xt;
            *(uint4*)&Ws[r * 36 + cq * 4] = wt;
        }
        __syncthreads();

#pragma unroll
        for (int ks = 0; ks < 4; ks++) {
            const int k0 = ks * 8;
            uint32_t a[4][4];
#pragma unroll
            for (int mi = 0; mi < 4; mi++) {
                int row = wm * 64 + mi * 16 + lr;
                a[mi][0] = Xs[row * 36 + k0 + lc];
                a[mi][1] = Xs[(row + 8) * 36 + k0 + lc];
                a[mi][2] = Xs[row * 36 + k0 + lc + 4];
                a[mi][3] = Xs[(row + 8) * 36 + k0 + lc + 4];
            }
            uint32_t b[4][2];
#pragma unroll
            for (int ni = 0; ni < 4; ni++) {
                int col = wn * 32 + ni * 8 + lr;
                b[ni][0] = Ws[col * 36 + k0 + lc];
                b[ni][1] = Ws[col * 36 + k0 + lc + 4];
            }
#pragma unroll
            for (int mi = 0; mi < 4; mi++)
#pragma unroll
                for (int ni = 0; ni < 4; ni++)
                    MMA_TF32(acc[mi][ni], a[mi], b[ni]);
        }
        __syncthreads();
    }

#pragma unroll
    for (int mi = 0; mi < 4; mi++) {
#pragma unroll
        for (int ni = 0; ni < 4; ni++) {
            int m = m0 + wm * 64 + mi * 16 + lr;
            int n = n0 + wn * 32 + ni * 8 + 2 * lc;
            float b0 = __ldg(&bias[n]), b1 = __ldg(&bias[n + 1]);
            int h = n >> 6, d = n & 63;
#pragma unroll
            for (int half = 0; half < 2; half++) {
                int mm = m + half * 8;
                int b_ = mm >> 11, s = mm & 2047;
                float2 val;
                val.x = (acc[mi][ni][half * 2 + 0] + b0) * oscale;
                val.y = (acc[mi][ni][half * 2 + 1] + b1) * oscale;
                *(float2*)&out[(((size_t)(b_ * HH + h) * SS) + s) * DKK + d] = val;
            }
        }
    }
}

// ---------------------------------------------------------------------------
// Causal flash attention on tf32 tensor cores.
// BM=128 (8 warps x 16 rows), BN=64, DK=64. Q pre-scaled by 1/sqrt(dk)*log2e,
// softmax uses ex2. All tiles in smem as tf32, word stride 68 (conflict-free).
// ---------------------------------------------------------------------------
__global__ __launch_bounds__(256, 2)
void flash_attn_tc(float* __restrict__ out)
{
    extern __shared__ uint32_t smu[];
    uint32_t* Qs = smu;                 // 128*68
    uint32_t* Ks = Qs + 128 * 68;       // 64*68
    uint32_t* Vs = Ks + 64 * 68;        // 64*68
    uint32_t* Ps = Vs + 64 * 68;        // 128*68

    const int bh = blockIdx.y;
    const int qt = blockIdx.x;
    const int m0 = qt * 128;

    const float* Qp = g_Q + (size_t)bh * SS * DKK;
    const float* Kp = g_K + (size_t)bh * SS * DKK;
    const float* Vp = g_V + (size_t)bh * SS * DKK;

    const int tid  = threadIdx.x;
    const int warp = tid >> 5;
    const int lane = tid & 31;
    const int lr = lane >> 2;         // 0..7
    const int lc = lane & 3;          // 0..3
    const int wrow = warp * 16;       // warp's row block

    // load Q tile (128x64), convert tf32
#pragma unroll
    for (int e = tid; e < 2048; e += 256) {
        int r = e >> 4, c4 = e & 15;
        float4 qv = *(const float4*)&Qp[(size_t)(m0 + r) * DKK + c4 * 4];
        uint4 qd;
        qd.x = f2tf32(qv.x); qd.y = f2tf32(qv.y);
        qd.z = f2tf32(qv.z); qd.w = f2tf32(qv.w);
        *(uint4*)&Qs[r * 68 + c4 * 4] = qd;
    }

    float m_i[2], l_i[2], o[8][4];
    m_i[0] = m_i[1] = -1e30f;
    l_i[0] = l_i[1] = 0.f;
#pragma unroll
    for (int nb = 0; nb < 8; nb++)
#pragma unroll
        for (int c = 0; c < 4; c++) o[nb][c] = 0.f;
    __syncthreads();

    const int ntiles = 2 * qt + 2;
    for (int t = 0; t < ntiles; t++) {
        const int n0 = t * 64;
        // load K,V tiles, convert tf32
#pragma unroll
        for (int e = tid; e < 1024; e += 256) {
            int r = e >> 4, c4 = e & 15;
            float4 kv = *(const float4*)&Kp[(size_t)(n0 + r) * DKK + c4 * 4];
            float4 vv = *(const float4*)&Vp[(size_t)(n0 + r) * DKK + c4 * 4];
            uint4 kd, vd;
            kd.x = f2tf32(kv.x); kd.y = f2tf32(kv.y);
            kd.z = f2tf32(kv.z); kd.w = f2tf32(kv.w);
            vd.x = f2tf32(vv.x); vd.y = f2tf32(vv.y);
            vd.z = f2tf32(vv.z); vd.w = f2tf32(vv.w);
            *(uint4*)&Ks[r * 68 + c4 * 4] = kd;
            *(uint4*)&Vs[r * 68 + c4 * 4] = vd;
        }
        __syncthreads();

        // S = Q K^T : warp computes 16x64
        float sc[8][4];
#pragma unroll
        for (int nb = 0; nb < 8; nb++)
#pragma unroll
            for (int c = 0; c < 4; c++) sc[nb][c] = 0.f;

#pragma unroll
        for (int ks = 0; ks < 8; ks++) {
            const int k0 = ks * 8;
            uint32_t a[4];
            a[0] = Qs[(wrow + lr) * 68 + k0 + lc];
            a[1] = Qs[(wrow + lr + 8) * 68 + k0 + lc];
            a[2] = Qs[(wrow + lr) * 68 + k0 + lc + 4];
            a[3] = Qs[(wrow + lr + 8) * 68 + k0 + lc + 4];
#pragma unroll
            for (int nb = 0; nb < 8; nb++) {
                uint32_t b[2];
                b[0] = Ks[(nb * 8 + lr) * 68 + k0 + lc];
                b[1] = Ks[(nb * 8 + lr) * 68 + k0 + lc + 4];
                MMA_TF32(sc[nb], a, b);
            }
        }

        // causal mask (only last two tiles)
        if (t >= 2 * qt) {
            const int row0 = m0 + wrow + lr;
            const int row1 = row0 + 8;
#pragma unroll
            for (int nb = 0; nb < 8; nb++) {
                int col = n0 + nb * 8 + 2 * lc;
                if (col > row0)     sc[nb][0] = -1e30f;
                if (col + 1 > row0) sc[nb][1] = -1e30f;
                if (col > row1)     sc[nb][2] = -1e30f;
                if (col + 1 > row1) sc[nb][3] = -1e30f;
            }
        }

        // online softmax (log2 domain; Q pre-scaled)
        float rmax[2] = {-1e30f, -1e30f};
#pragma unroll
        for (int nb = 0; nb < 8; nb++) {
            rmax[0] = fmaxf(rmax[0], fmaxf(sc[nb][0], sc[nb][1]));
            rmax[1] = fmaxf(rmax[1], fmaxf(sc[nb][2], sc[nb][3]));
        }
#pragma unroll
        for (int off = 1; off < 4; off <<= 1) {
            rmax[0] = fmaxf(rmax[0], __shfl_xor_sync(0xffffffffu, rmax[0], off));
            rmax[1] = fmaxf(rmax[1], __shfl_xor_sync(0xffffffffu, rmax[1], off));
        }
        float mnew0 = fmaxf(m_i[0], rmax[0]);
        float mnew1 = fmaxf(m_i[1], rmax[1]);
        float corr0 = ex2(m_i[0] - mnew0);
        float corr1 = ex2(m_i[1] - mnew1);
        m_i[0] = mnew0; m_i[1] = mnew1;

        float rsum[2] = {0.f, 0.f};
#pragma unroll
        for (int nb = 0; nb < 8; nb++) {
            float p0 = ex2(sc[nb][0] - mnew0);
            float p1 = ex2(sc[nb][1] - mnew0);
            float p2 = ex2(sc[nb][2] - mnew1);
            float p3 = ex2(sc[nb][3] - mnew1);
            rsum[0] += p0 + p1;
            rsum[1] += p2 + p3;
            uint2 w0, w1;
            w0.x = f2tf32(p0); w0.y = f2tf32(p1);
            w1.x = f2tf32(p2); w1.y = f2tf32(p3);
            *(uint2*)&Ps[(wrow + lr) * 68 + nb * 8 + 2 * lc] = w0;
            *(uint2*)&Ps[(wrow + lr + 8) * 68 + nb * 8 + 2 * lc] = w1;
        }
#pragma unroll
        for (int off = 1; off < 4; off <<= 1) {
            rsum[0] += __shfl_xor_sync(0xffffffffu, rsum[0], off);
            rsum[1] += __shfl_xor_sync(0xffffffffu, rsum[1], off);
        }
        l_i[0] = l_i[0] * corr0 + rsum[0];
        l_i[1] = l_i[1] * corr1 + rsum[1];
#pragma unroll
        for (int nb = 0; nb < 8; nb++) {
            o[nb][0] *= corr0; o[nb][1] *= corr0;
            o[nb][2] *= corr1; o[nb][3] *= corr1;
        }
        __syncwarp();

        // O += P V  (P warp-private rows in smem)
#pragma unroll
        for (int ks = 0; ks < 8; ks++) {
            const int k0 = ks * 8;
            uint32_t a[4];
            a[0] = Ps[(wrow + lr) * 68 + k0 + lc];
            a[1] = Ps[(wrow + lr + 8) * 68 + k0 + lc];
            a[2] = Ps[(wrow + lr) * 68 + k0 + lc + 4];
            a[3] = Ps[(wrow + lr + 8) * 68 + k0 + lc + 4];
#pragma unroll
            for (int nb = 0; nb < 8; nb++) {
                uint32_t b[2];
                b[0] = Vs[(k0 + lc) * 68 + nb * 8 + lr];
                b[1] = Vs[(k0 + lc + 4) * 68 + nb * 8 + lr];
                MMA_TF32(o[nb], a, b);
            }
        }
        __syncthreads();   // protect Ks/Vs for next iteration
    }

    // epilogue
    const int b = bh >> 4;
    const int h = bh & 15;
    const float inv0 = 1.0f / l_i[0];
    const float inv1 = 1.0f / l_i[1];
    const int row0 = m0 + wrow + lr;
#pragma unroll
    for (int nb = 0; nb < 8; nb++) {
        int d = h * DKK + nb * 8 + 2 * lc;
        float2 v0, v1;
        v0.x = o[nb][0] * inv0; v0.y = o[nb][1] * inv0;
        v1.x = o[nb][2] * inv1; v1.y = o[nb][3] * inv1;
        *(float2*)&out[((size_t)(b * SS + row0)) * DD + d] = v0;
        *(float2*)&out[((size_t)(b * SS + row0 + 8)) * DD + d] = v1;
    }
}

// ---------------------------------------------------------------------------
extern "C" void kernel_launch(void* const* d_in, const int* in_sizes, int n_in,
                              void* d_out, int out_size)
{
    const float* q  = (const float*)d_in[0];
    const float* v  = (const float*)d_in[1];
    const float* k  = (const float*)d_in[2];
    // d_in[3] = attn_mask (causal, known analytically) — unused
    const float* Wq = (const float*)d_in[4];
    const float* bq = (const float*)d_in[5];
    const float* Wk = (const float*)d_in[6];
    const float* bk = (const float*)d_in[7];
    const float* Wv = (const float*)d_in[8];
    const float* bv = (const float*)d_in[9];
    float* out = (float*)d_out;

    dim3 gGemm(MTOT / 128, DD / 128, 3);
    qkv_gemm_tf32<<<gGemm, 256>>>(q, k, v, Wq, bq, Wk, bk, Wv, bv);

    const int smemBytes = (128 * 68 + 64 * 68 + 64 * 68 + 128 * 68) * sizeof(uint32_t);
    cudaFuncSetAttribute(flash_attn_tc, cudaFuncAttributeMaxDynamicSharedMemorySize, smemBytes);
    dim3 gAttn(SS / 128, BB * HH);
    flash_attn_tc<<<gAttn, 256, smemBytes>>>(out);
}

// round 4
// speedup vs baseline: 4.0210x; 1.1362x over previous
#include <cuda_runtime.h>
#include <cuda_bf16.h>
#include <cstdint>

#define BB 4
#define SS 2048
#define DD 1024
#define HH 16
#define DKK 64
#define MTOT (BB*SS)          // 8192

// log2(e) / sqrt(64) folded into Q projection
#define QSCALE 0.18033688011112042f

// Head-major scratch [B*H, S, DK]
__device__ float g_Q[(size_t)MTOT * DD];
__device__ float g_K[(size_t)MTOT * DD];
__device__ float g_V[(size_t)MTOT * DD];

__device__ __forceinline__ uint32_t f2tf32(float f) {
    uint32_t u;
    asm("cvt.rna.tf32.f32 %0, %1;" : "=r"(u) : "f"(f));
    return u;
}
__device__ __forceinline__ float ex2(float x) {
    float y;
    asm("ex2.approx.ftz.f32 %0, %1;" : "=f"(y) : "f"(x));
    return y;
}

#define MMA_TF32(d, a, b)                                                     \
    asm volatile("mma.sync.aligned.m16n8k8.row.col.f32.tf32.tf32.f32 "        \
                 "{%0,%1,%2,%3}, {%4,%5,%6,%7}, {%8,%9}, {%0,%1,%2,%3};"      \
                 : "+f"(d[0]), "+f"(d[1]), "+f"(d[2]), "+f"(d[3])             \
                 : "r"(a[0]), "r"(a[1]), "r"(a[2]), "r"(a[3]),                \
                   "r"(b[0]), "r"(b[1]));

// ---------------------------------------------------------------------------
// QKV projection, tf32 tensor cores (unchanged from R3; ~385us).
// ---------------------------------------------------------------------------
__global__ __launch_bounds__(256, 2)
void qkv_gemm_tf32(const float* __restrict__ q,
                   const float* __restrict__ k,
                   const float* __restrict__ v,
                   const float* __restrict__ Wq, const float* __restrict__ bq,
                   const float* __restrict__ Wk, const float* __restrict__ bk,
                   const float* __restrict__ Wv, const float* __restrict__ bv)
{
    __shared__ uint32_t Xs[128 * 36];
    __shared__ uint32_t Ws[128 * 36];

    const float* X; const float* W; const float* bias; float* out;
    int z = blockIdx.z;
    float oscale;
    if (z == 0)      { X = q; W = Wq; bias = bq; out = g_Q; oscale = QSCALE; }
    else if (z == 1) { X = k; W = Wk; bias = bk; out = g_K; oscale = 1.f; }
    else             { X = v; W = Wv; bias = bv; out = g_V; oscale = 1.f; }

    const int m0 = blockIdx.x * 128;
    const int n0 = blockIdx.y * 128;
    const int tid  = threadIdx.x;
    const int warp = tid >> 5;
    const int lane = tid & 31;
    const int wm = warp >> 2;
    const int wn = warp & 3;
    const int lr = lane >> 2;
    const int lc = lane & 3;

    float acc[4][4][4];
#pragma unroll
    for (int mi = 0; mi < 4; mi++)
#pragma unroll
        for (int ni = 0; ni < 4; ni++)
#pragma unroll
            for (int c = 0; c < 4; c++) acc[mi][ni][c] = 0.f;

    for (int kc = 0; kc < DD; kc += 32) {
#pragma unroll
        for (int e = tid; e < 1024; e += 256) {
            int r  = e >> 3;
            int cq = e & 7;
            float4 xv = *(const float4*)&X[(size_t)(m0 + r) * DD + kc + cq * 4];
            float4 wv = *(const float4*)&W[(size_t)(n0 + r) * DD + kc + cq * 4];
            uint4 xt, wt;
            xt.x = f2tf32(xv.x); xt.y = f2tf32(xv.y);
            xt.z = f2tf32(xv.z); xt.w = f2tf32(xv.w);
            wt.x = f2tf32(wv.x); wt.y = f2tf32(wv.y);
            wt.z = f2tf32(wv.z); wt.w = f2tf32(wv.w);
            *(uint4*)&Xs[r * 36 + cq * 4] = xt;
            *(uint4*)&Ws[r * 36 + cq * 4] = wt;
        }
        __syncthreads();

#pragma unroll
        for (int ks = 0; ks < 4; ks++) {
            const int k0 = ks * 8;
            uint32_t a[4][4];
#pragma unroll
            for (int mi = 0; mi < 4; mi++) {
                int row = wm * 64 + mi * 16 + lr;
                a[mi][0] = Xs[row * 36 + k0 + lc];
                a[mi][1] = Xs[(row + 8) * 36 + k0 + lc];
                a[mi][2] = Xs[row * 36 + k0 + lc + 4];
                a[mi][3] = Xs[(row + 8) * 36 + k0 + lc + 4];
            }
            uint32_t b[4][2];
#pragma unroll
            for (int ni = 0; ni < 4; ni++) {
                int col = wn * 32 + ni * 8 + lr;
                b[ni][0] = Ws[col * 36 + k0 + lc];
                b[ni][1] = Ws[col * 36 + k0 + lc + 4];
            }
#pragma unroll
            for (int mi = 0; mi < 4; mi++)
#pragma unroll
                for (int ni = 0; ni < 4; ni++)
                    MMA_TF32(acc[mi][ni], a[mi], b[ni]);
        }
        __syncthreads();
    }

#pragma unroll
    for (int mi = 0; mi < 4; mi++) {
#pragma unroll
        for (int ni = 0; ni < 4; ni++) {
            int m = m0 + wm * 64 + mi * 16 + lr;
            int n = n0 + wn * 32 + ni * 8 + 2 * lc;
            float b0 = __ldg(&bias[n]), b1 = __ldg(&bias[n + 1]);
            int h = n >> 6, d = n & 63;
#pragma unroll
            for (int half = 0; half < 2; half++) {
                int mm = m + half * 8;
                int b_ = mm >> 11, s = mm & 2047;
                float2 val;
                val.x = (acc[mi][ni][half * 2 + 0] + b0) * oscale;
                val.y = (acc[mi][ni][half * 2 + 1] + b1) * oscale;
                *(float2*)&out[(((size_t)(b_ * HH + h) * SS) + s) * DKK + d] = val;
            }
        }
    }
}

// ---------------------------------------------------------------------------
// Causal flash attention, tf32 MMA. BM=128, 4 warps, warp tile 32x64.
// Q/K/P smem stride 68 (banks 4*row+k: conflict-free fragment reads).
// V smem stride 72 (banks 8*lc+lr on transposed B reads: conflict-free).
// B fragments (K and V) loaded once, reused across both 16-row m-blocks.
// ---------------------------------------------------------------------------
__global__ __launch_bounds__(128)
void flash_attn_tc(float* __restrict__ out)
{
    extern __shared__ uint32_t smu[];
    uint32_t* Qs = smu;                 // 128*68
    uint32_t* Ks = Qs + 128 * 68;       // 64*68
    uint32_t* Vs = Ks + 64 * 68;        // 64*72
    uint32_t* Ps = Vs + 64 * 72;        // 128*68

    const int bh = blockIdx.y;
    const int qt = blockIdx.x;
    const int m0 = qt * 128;

    const float* Qp = g_Q + (size_t)bh * SS * DKK;
    const float* Kp = g_K + (size_t)bh * SS * DKK;
    const float* Vp = g_V + (size_t)bh * SS * DKK;

    const int tid  = threadIdx.x;
    const int warp = tid >> 5;
    const int lane = tid & 31;
    const int lr = lane >> 2;         // 0..7
    const int lc = lane & 3;          // 0..3
    const int wrow = warp * 32;       // warp's 32-row block

    // load Q tile (128x64) as tf32
#pragma unroll
    for (int e = tid; e < 2048; e += 128) {
        int r = e >> 4, c4 = e & 15;
        float4 qv = *(const float4*)&Qp[(size_t)(m0 + r) * DKK + c4 * 4];
        uint4 qd;
        qd.x = f2tf32(qv.x); qd.y = f2tf32(qv.y);
        qd.z = f2tf32(qv.z); qd.w = f2tf32(qv.w);
        *(uint4*)&Qs[r * 68 + c4 * 4] = qd;
    }

    // per-thread softmax state: rows mi*16 + {lr, lr+8}, index = mi*2+half
    float m_i[4], l_i[4];
    float o[2][8][4];
#pragma unroll
    for (int i = 0; i < 4; i++) { m_i[i] = -1e30f; l_i[i] = 0.f; }
#pragma unroll
    for (int mi = 0; mi < 2; mi++)
#pragma unroll
        for (int nb = 0; nb < 8; nb++)
#pragma unroll
            for (int c = 0; c < 4; c++) o[mi][nb][c] = 0.f;
    __syncthreads();

    const int ntiles = 2 * qt + 2;
    for (int t = 0; t < ntiles; t++) {
        const int n0 = t * 64;
        // fill K (stride 68) and V (stride 72), tf32
#pragma unroll
        for (int e = tid; e < 1024; e += 128) {
            int r = e >> 4, c4 = e & 15;
            float4 kv = *(const float4*)&Kp[(size_t)(n0 + r) * DKK + c4 * 4];
            float4 vv = *(const float4*)&Vp[(size_t)(n0 + r) * DKK + c4 * 4];
            uint4 kd, vd;
            kd.x = f2tf32(kv.x); kd.y = f2tf32(kv.y);
            kd.z = f2tf32(kv.z); kd.w = f2tf32(kv.w);
            vd.x = f2tf32(vv.x); vd.y = f2tf32(vv.y);
            vd.z = f2tf32(vv.z); vd.w = f2tf32(vv.w);
            *(uint4*)&Ks[r * 68 + c4 * 4] = kd;
            *(uint4*)&Vs[r * 72 + c4 * 4] = vd;
        }
        __syncthreads();

        // S = Q K^T : warp computes 32x64
        float sc[2][8][4];
#pragma unroll
        for (int mi = 0; mi < 2; mi++)
#pragma unroll
            for (int nb = 0; nb < 8; nb++)
#pragma unroll
                for (int c = 0; c < 4; c++) sc[mi][nb][c] = 0.f;

#pragma unroll
        for (int ks = 0; ks < 8; ks++) {
            const int k0 = ks * 8;
            uint32_t a[2][4];
#pragma unroll
            for (int mi = 0; mi < 2; mi++) {
                int row = wrow + mi * 16 + lr;
                a[mi][0] = Qs[row * 68 + k0 + lc];
                a[mi][1] = Qs[(row + 8) * 68 + k0 + lc];
                a[mi][2] = Qs[row * 68 + k0 + lc + 4];
                a[mi][3] = Qs[(row + 8) * 68 + k0 + lc + 4];
            }
#pragma unroll
            for (int nb = 0; nb < 8; nb++) {
                uint32_t b[2];
                b[0] = Ks[(nb * 8 + lr) * 68 + k0 + lc];
                b[1] = Ks[(nb * 8 + lr) * 68 + k0 + lc + 4];
                MMA_TF32(sc[0][nb], a[0], b);
                MMA_TF32(sc[1][nb], a[1], b);
            }
        }

        // causal mask (only the last two tiles touch the diagonal)
        if (t >= 2 * qt) {
#pragma unroll
            for (int mi = 0; mi < 2; mi++) {
                const int row0 = m0 + wrow + mi * 16 + lr;
                const int row1 = row0 + 8;
#pragma unroll
                for (int nb = 0; nb < 8; nb++) {
                    int col = n0 + nb * 8 + 2 * lc;
                    if (col > row0)     sc[mi][nb][0] = -1e30f;
                    if (col + 1 > row0) sc[mi][nb][1] = -1e30f;
                    if (col > row1)     sc[mi][nb][2] = -1e30f;
                    if (col + 1 > row1) sc[mi][nb][3] = -1e30f;
                }
            }
        }

        // online softmax (log2 domain; Q pre-scaled by QSCALE)
#pragma unroll
        for (int mi = 0; mi < 2; mi++) {
            float rmax0 = -1e30f, rmax1 = -1e30f;
#pragma unroll
            for (int nb = 0; nb < 8; nb++) {
                rmax0 = fmaxf(rmax0, fmaxf(sc[mi][nb][0], sc[mi][nb][1]));
                rmax1 = fmaxf(rmax1, fmaxf(sc[mi][nb][2], sc[mi][nb][3]));
            }
#pragma unroll
            for (int off = 1; off < 4; off <<= 1) {
                rmax0 = fmaxf(rmax0, __shfl_xor_sync(0xffffffffu, rmax0, off));
                rmax1 = fmaxf(rmax1, __shfl_xor_sync(0xffffffffu, rmax1, off));
            }
            float mnew0 = fmaxf(m_i[mi * 2 + 0], rmax0);
            float mnew1 = fmaxf(m_i[mi * 2 + 1], rmax1);
            float corr0 = ex2(m_i[mi * 2 + 0] - mnew0);
            float corr1 = ex2(m_i[mi * 2 + 1] - mnew1);
            m_i[mi * 2 + 0] = mnew0; m_i[mi * 2 + 1] = mnew1;

            float rsum0 = 0.f, rsum1 = 0.f;
            const int prow = (wrow + mi * 16 + lr) * 68;
#pragma unroll
            for (int nb = 0; nb < 8; nb++) {
                float p0 = ex2(sc[mi][nb][0] - mnew0);
                float p1 = ex2(sc[mi][nb][1] - mnew0);
                float p2 = ex2(sc[mi][nb][2] - mnew1);
                float p3 = ex2(sc[mi][nb][3] - mnew1);
                rsum0 += p0 + p1;
                rsum1 += p2 + p3;
                uint2 w0, w1;
                w0.x = f2tf32(p0); w0.y = f2tf32(p1);
                w1.x = f2tf32(p2); w1.y = f2tf32(p3);
                *(uint2*)&Ps[prow + nb * 8 + 2 * lc] = w0;
                *(uint2*)&Ps[prow + 8 * 68 + nb * 8 + 2 * lc] = w1;
            }
#pragma unroll
            for (int off = 1; off < 4; off <<= 1) {
                rsum0 += __shfl_xor_sync(0xffffffffu, rsum0, off);
                rsum1 += __shfl_xor_sync(0xffffffffu, rsum1, off);
            }
            l_i[mi * 2 + 0] = l_i[mi * 2 + 0] * corr0 + rsum0;
            l_i[mi * 2 + 1] = l_i[mi * 2 + 1] * corr1 + rsum1;
#pragma unroll
            for (int nb = 0; nb < 8; nb++) {
                o[mi][nb][0] *= corr0; o[mi][nb][1] *= corr0;
                o[mi][nb][2] *= corr1; o[mi][nb][3] *= corr1;
            }
        }
        __syncwarp();   // P rows are warp-private

        // O += P V
#pragma unroll
        for (int ks = 0; ks < 8; ks++) {
            const int k0 = ks * 8;
            uint32_t a[2][4];
#pragma unroll
            for (int mi = 0; mi < 2; mi++) {
                int row = wrow + mi * 16 + lr;
                a[mi][0] = Ps[row * 68 + k0 + lc];
                a[mi][1] = Ps[(row + 8) * 68 + k0 + lc];
                a[mi][2] = Ps[row * 68 + k0 + lc + 4];
                a[mi][3] = Ps[(row + 8) * 68 + k0 + lc + 4];
            }
#pragma unroll
            for (int nb = 0; nb < 8; nb++) {
                uint32_t b[2];
                b[0] = Vs[(k0 + lc) * 72 + nb * 8 + lr];
                b[1] = Vs[(k0 + lc + 4) * 72 + nb * 8 + lr];
                MMA_TF32(o[0][nb], a[0], b);
                MMA_TF32(o[1][nb], a[1], b);
            }
        }
        __syncthreads();   // protect Ks/Vs for next iteration
    }

    // epilogue
    const int b = bh >> 4;
    const int h = bh & 15;
#pragma unroll
    for (int mi = 0; mi < 2; mi++) {
        const float inv0 = 1.0f / l_i[mi * 2 + 0];
        const float inv1 = 1.0f / l_i[mi * 2 + 1];
        const int row0 = m0 + wrow + mi * 16 + lr;
#pragma unroll
        for (int nb = 0; nb < 8; nb++) {
            int d = h * DKK + nb * 8 + 2 * lc;
            float2 v0, v1;
            v0.x = o[mi][nb][0] * inv0; v0.y = o[mi][nb][1] * inv0;
            v1.x = o[mi][nb][2] * inv1; v1.y = o[mi][nb][3] * inv1;
            *(float2*)&out[((size_t)(b * SS + row0)) * DD + d] = v0;
            *(float2*)&out[((size_t)(b * SS + row0 + 8)) * DD + d] = v1;
        }
    }
}

// ---------------------------------------------------------------------------
extern "C" void kernel_launch(void* const* d_in, const int* in_sizes, int n_in,
                              void* d_out, int out_size)
{
    const float* q  = (const float*)d_in[0];
    const float* v  = (const float*)d_in[1];
    const float* k  = (const float*)d_in[2];
    // d_in[3] = attn_mask (causal, known analytically) — unused
    const float* Wq = (const float*)d_in[4];
    const float* bq = (const float*)d_in[5];
    const float* Wk = (const float*)d_in[6];
    const float* bk = (const float*)d_in[7];
    const float* Wv = (const float*)d_in[8];
    const float* bv = (const float*)d_in[9];
    float* out = (float*)d_out;

    dim3 gGemm(MTOT / 128, DD / 128, 3);
    qkv_gemm_tf32<<<gGemm, 256>>>(q, k, v, Wq, bq, Wk, bk, Wv, bv);

    const int smemBytes = (128 * 68 + 64 * 68 + 64 * 72 + 128 * 68) * sizeof(uint32_t);
    cudaFuncSetAttribute(flash_attn_tc, cudaFuncAttributeMaxDynamicSharedMemorySize, smemBytes);
    dim3 gAttn(SS / 128, BB * HH);
    flash_attn_tc<<<gAttn, 128, smemBytes>>>(out);
}

// round 5
// speedup vs baseline: 4.3877x; 1.0912x over previous
#include <cuda_runtime.h>
#include <cuda_bf16.h>
#include <cstdint>

#define BB 4
#define SS 2048
#define DD 1024
#define HH 16
#define DKK 64
#define MTOT (BB*SS)          // 8192

// log2(e) / sqrt(64) folded into Q projection
#define QSCALE 0.18033688011112042f

// Scratch (all values stored as tf32-rna-rounded fp32 bit patterns)
__device__ float g_Q[(size_t)MTOT * DD];
__device__ float g_K[(size_t)MTOT * DD];
__device__ float g_V[(size_t)MTOT * DD];
__device__ float g_X[3][(size_t)MTOT * DD];   // pre-rounded q,k,v inputs
__device__ float g_W[3][(size_t)DD * DD];     // pre-rounded Wq,Wk,Wv

__device__ __forceinline__ uint32_t f2tf32(float f) {
    uint32_t u;
    asm("cvt.rna.tf32.f32 %0, %1;" : "=r"(u) : "f"(f));
    return u;
}
__device__ __forceinline__ float ex2(float x) {
    float y;
    asm("ex2.approx.ftz.f32 %0, %1;" : "=f"(y) : "f"(x));
    return y;
}
__device__ __forceinline__ uint32_t saddr(const void* p) {
    return (uint32_t)__cvta_generic_to_shared(p);
}
__device__ __forceinline__ void cp16(uint32_t s, const void* g) {
    asm volatile("cp.async.cg.shared.global [%0], [%1], 16;" :: "r"(s), "l"(g));
}
#define CP_COMMIT() asm volatile("cp.async.commit_group;")
#define CP_WAIT1()  asm volatile("cp.async.wait_group 1;")

#define MMA_TF32(d, a, b)                                                     \
    asm volatile("mma.sync.aligned.m16n8k8.row.col.f32.tf32.tf32.f32 "        \
                 "{%0,%1,%2,%3}, {%4,%5,%6,%7}, {%8,%9}, {%0,%1,%2,%3};"      \
                 : "+f"(d[0]), "+f"(d[1]), "+f"(d[2]), "+f"(d[3])             \
                 : "r"(a[0]), "r"(a[1]), "r"(a[2]), "r"(a[3]),                \
                   "r"(b[0]), "r"(b[1]));

// ---------------------------------------------------------------------------
// Pre-round pass: fp32 -> tf32(rna) bit patterns, so all later cp.async
// consumers can feed smem directly into MMA without per-fragment cvts.
// ---------------------------------------------------------------------------
__global__ void cvt_prepass(const float* __restrict__ q,
                            const float* __restrict__ k,
                            const float* __restrict__ v,
                            const float* __restrict__ Wq,
                            const float* __restrict__ Wk,
                            const float* __restrict__ Wv)
{
    const float* src; float* dst; size_t n;
    switch (blockIdx.y) {
        case 0: src = q;  dst = g_X[0]; n = (size_t)MTOT * DD; break;
        case 1: src = k;  dst = g_X[1]; n = (size_t)MTOT * DD; break;
        case 2: src = v;  dst = g_X[2]; n = (size_t)MTOT * DD; break;
        case 3: src = Wq; dst = g_W[0]; n = (size_t)DD * DD;   break;
        case 4: src = Wk; dst = g_W[1]; n = (size_t)DD * DD;   break;
        default: src = Wv; dst = g_W[2]; n = (size_t)DD * DD;  break;
    }
    const float4* s4 = (const float4*)src;
    float4* d4 = (float4*)dst;
    size_t n4 = n >> 2;
    size_t stride = (size_t)gridDim.x * blockDim.x;
    for (size_t i = (size_t)blockIdx.x * blockDim.x + threadIdx.x; i < n4; i += stride) {
        float4 val = s4[i];
        float4 o;
        o.x = __uint_as_float(f2tf32(val.x));
        o.y = __uint_as_float(f2tf32(val.y));
        o.z = __uint_as_float(f2tf32(val.z));
        o.w = __uint_as_float(f2tf32(val.w));
        d4[i] = o;
    }
}

// ---------------------------------------------------------------------------
// QKV projection, tf32 MMA, 2-stage cp.async pipeline.
// Operands pre-rounded; outputs rounded in epilogue (attention feeds raw).
// ---------------------------------------------------------------------------
__global__ __launch_bounds__(256, 2)
void qkv_gemm_tf32(const float* __restrict__ bq,
                   const float* __restrict__ bk,
                   const float* __restrict__ bv)
{
    extern __shared__ uint32_t dsm[];
    uint32_t* Xs0 = dsm;                      // 2 stages x 128*36
    uint32_t* Ws0 = dsm + 2 * 128 * 36;

    const int z = blockIdx.z;
    const float* X = g_X[z];
    const float* W = g_W[z];
    const float* bias = (z == 0) ? bq : (z == 1) ? bk : bv;
    float* out = (z == 0) ? g_Q : (z == 1) ? g_K : g_V;
    const float oscale = (z == 0) ? QSCALE : 1.f;

    const int m0 = blockIdx.x * 128;
    const int n0 = blockIdx.y * 128;
    const int tid  = threadIdx.x;
    const int warp = tid >> 5;
    const int lane = tid & 31;
    const int wm = warp >> 2;
    const int wn = warp & 3;
    const int lr = lane >> 2;
    const int lc = lane & 3;

    float acc[4][4][4];
#pragma unroll
    for (int mi = 0; mi < 4; mi++)
#pragma unroll
        for (int ni = 0; ni < 4; ni++)
#pragma unroll
            for (int c = 0; c < 4; c++) acc[mi][ni][c] = 0.f;

    // issue one K-chunk (32 wide) into stage s
    auto issue = [&](int it) {
        const int kc = it * 32;
        const int s  = it & 1;
        uint32_t* Xs = Xs0 + s * 128 * 36;
        uint32_t* Ws = Ws0 + s * 128 * 36;
#pragma unroll
        for (int e = tid; e < 1024; e += 256) {
            int r = e >> 3, cq = e & 7;
            cp16(saddr(&Xs[r * 36 + cq * 4]), &X[(size_t)(m0 + r) * DD + kc + cq * 4]);
            cp16(saddr(&Ws[r * 36 + cq * 4]), &W[(size_t)(n0 + r) * DD + kc + cq * 4]);
        }
    };

    issue(0); CP_COMMIT();
    for (int it = 0; it < 32; it++) {
        if (it + 1 < 32) issue(it + 1);
        CP_COMMIT();
        CP_WAIT1();
        __syncthreads();
        const uint32_t* Xc = Xs0 + (it & 1) * 128 * 36;
        const uint32_t* Wc = Ws0 + (it & 1) * 128 * 36;
#pragma unroll
        for (int ks = 0; ks < 4; ks++) {
            const int k0 = ks * 8;
            uint32_t a[4][4];
#pragma unroll
            for (int mi = 0; mi < 4; mi++) {
                int row = wm * 64 + mi * 16 + lr;
                a[mi][0] = Xc[row * 36 + k0 + lc];
                a[mi][1] = Xc[(row + 8) * 36 + k0 + lc];
                a[mi][2] = Xc[row * 36 + k0 + lc + 4];
                a[mi][3] = Xc[(row + 8) * 36 + k0 + lc + 4];
            }
            uint32_t b[4][2];
#pragma unroll
            for (int ni = 0; ni < 4; ni++) {
                int col = wn * 32 + ni * 8 + lr;
                b[ni][0] = Wc[col * 36 + k0 + lc];
                b[ni][1] = Wc[col * 36 + k0 + lc + 4];
            }
#pragma unroll
            for (int mi = 0; mi < 4; mi++)
#pragma unroll
                for (int ni = 0; ni < 4; ni++)
                    MMA_TF32(acc[mi][ni], a[mi], b[ni]);
        }
        __syncthreads();
    }

    // epilogue: bias, scale, tf32-round, scatter head-major
#pragma unroll
    for (int mi = 0; mi < 4; mi++) {
#pragma unroll
        for (int ni = 0; ni < 4; ni++) {
            int m = m0 + wm * 64 + mi * 16 + lr;
            int n = n0 + wn * 32 + ni * 8 + 2 * lc;
            float b0 = __ldg(&bias[n]), b1 = __ldg(&bias[n + 1]);
            int h = n >> 6, d = n & 63;
#pragma unroll
            for (int half = 0; half < 2; half++) {
                int mm = m + half * 8;
                int b_ = mm >> 11, s = mm & 2047;
                float2 val;
                val.x = __uint_as_float(f2tf32((acc[mi][ni][half * 2 + 0] + b0) * oscale));
                val.y = __uint_as_float(f2tf32((acc[mi][ni][half * 2 + 1] + b1) * oscale));
                *(float2*)&out[(((size_t)(b_ * HH + h) * SS) + s) * DKK + d] = val;
            }
        }
    }
}

// ---------------------------------------------------------------------------
// Causal flash attention, tf32 MMA, split-issue cp.async pipeline.
// BM=128, 4 warps, warp tile 32x64. V(t) loads during QK(t); K(t+1) loads
// during softmax+PV(t). Single-buffered K/V; wait_group 1 at phase bounds.
// ---------------------------------------------------------------------------
__global__ __launch_bounds__(128)
void flash_attn_tc(float* __restrict__ out)
{
    extern __shared__ uint32_t smu[];
    uint32_t* Qs = smu;                 // 128*68
    uint32_t* Ks = Qs + 128 * 68;       // 64*68
    uint32_t* Vs = Ks + 64 * 68;        // 64*72
    uint32_t* Ps = Vs + 64 * 72;        // 128*68

    const int bh = blockIdx.y;
    const int qt = blockIdx.x;
    const int m0 = qt * 128;

    const float* Qp = g_Q + (size_t)bh * SS * DKK;
    const float* Kp = g_K + (size_t)bh * SS * DKK;
    const float* Vp = g_V + (size_t)bh * SS * DKK;

    const int tid  = threadIdx.x;
    const int warp = tid >> 5;
    const int lane = tid & 31;
    const int lr = lane >> 2;
    const int lc = lane & 3;
    const int wrow = warp * 32;

    auto issueK = [&](int t) {
        const int n0 = t * 64;
#pragma unroll
        for (int e = tid; e < 1024; e += 128) {
            int r = e >> 4, c4 = e & 15;
            cp16(saddr(&Ks[r * 68 + c4 * 4]), &Kp[(size_t)(n0 + r) * DKK + c4 * 4]);
        }
    };
    auto issueV = [&](int t) {
        const int n0 = t * 64;
#pragma unroll
        for (int e = tid; e < 1024; e += 128) {
            int r = e >> 4, c4 = e & 15;
            cp16(saddr(&Vs[r * 72 + c4 * 4]), &Vp[(size_t)(n0 + r) * DKK + c4 * 4]);
        }
    };

    // prologue: Q group, K(0) group, V(0) group
#pragma unroll
    for (int e = tid; e < 2048; e += 128) {
        int r = e >> 4, c4 = e & 15;
        cp16(saddr(&Qs[r * 68 + c4 * 4]), &Qp[(size_t)(m0 + r) * DKK + c4 * 4]);
    }
    CP_COMMIT();
    issueK(0); CP_COMMIT();
    issueV(0); CP_COMMIT();

    float m_i[4], l_i[4];
    float o[2][8][4];
#pragma unroll
    for (int i = 0; i < 4; i++) { m_i[i] = -1e30f; l_i[i] = 0.f; }
#pragma unroll
    for (int mi = 0; mi < 2; mi++)
#pragma unroll
        for (int nb = 0; nb < 8; nb++)
#pragma unroll
            for (int c = 0; c < 4; c++) o[mi][nb][c] = 0.f;

    const int ntiles = 2 * qt + 2;
    for (int t = 0; t < ntiles; t++) {
        const int n0 = t * 64;

        CP_WAIT1();           // Q + K(t) complete (V(t) may pend)
        __syncthreads();

        // S = Q K^T : warp computes 32x64
        float sc[2][8][4];
#pragma unroll
        for (int mi = 0; mi < 2; mi++)
#pragma unroll
            for (int nb = 0; nb < 8; nb++)
#pragma unroll
                for (int c = 0; c < 4; c++) sc[mi][nb][c] = 0.f;

#pragma unroll
        for (int ks = 0; ks < 8; ks++) {
            const int k0 = ks * 8;
            uint32_t a[2][4];
#pragma unroll
            for (int mi = 0; mi < 2; mi++) {
                int row = wrow + mi * 16 + lr;
                a[mi][0] = Qs[row * 68 + k0 + lc];
                a[mi][1] = Qs[(row + 8) * 68 + k0 + lc];
                a[mi][2] = Qs[row * 68 + k0 + lc + 4];
                a[mi][3] = Qs[(row + 8) * 68 + k0 + lc + 4];
            }
#pragma unroll
            for (int nb = 0; nb < 8; nb++) {
                uint32_t b[2];
                b[0] = Ks[(nb * 8 + lr) * 68 + k0 + lc];
                b[1] = Ks[(nb * 8 + lr) * 68 + k0 + lc + 4];
                MMA_TF32(sc[0][nb], a[0], b);
                MMA_TF32(sc[1][nb], a[1], b);
            }
        }
        __syncthreads();      // all warps done reading Ks
        if (t + 1 < ntiles) issueK(t + 1);
        CP_COMMIT();

        // causal mask (diagonal tiles only)
        if (t >= 2 * qt) {
#pragma unroll
            for (int mi = 0; mi < 2; mi++) {
                const int row0 = m0 + wrow + mi * 16 + lr;
                const int row1 = row0 + 8;
#pragma unroll
                for (int nb = 0; nb < 8; nb++) {
                    int col = n0 + nb * 8 + 2 * lc;
                    if (col > row0)     sc[mi][nb][0] = -1e30f;
                    if (col + 1 > row0) sc[mi][nb][1] = -1e30f;
                    if (col > row1)     sc[mi][nb][2] = -1e30f;
                    if (col + 1 > row1) sc[mi][nb][3] = -1e30f;
                }
            }
        }

        // online softmax (log2 domain; Q pre-scaled by QSCALE)
#pragma unroll
        for (int mi = 0; mi < 2; mi++) {
            float rmax0 = -1e30f, rmax1 = -1e30f;
#pragma unroll
            for (int nb = 0; nb < 8; nb++) {
                rmax0 = fmaxf(rmax0, fmaxf(sc[mi][nb][0], sc[mi][nb][1]));
                rmax1 = fmaxf(rmax1, fmaxf(sc[mi][nb][2], sc[mi][nb][3]));
            }
#pragma unroll
            for (int off = 1; off < 4; off <<= 1) {
                rmax0 = fmaxf(rmax0, __shfl_xor_sync(0xffffffffu, rmax0, off));
                rmax1 = fmaxf(rmax1, __shfl_xor_sync(0xffffffffu, rmax1, off));
            }
            float mnew0 = fmaxf(m_i[mi * 2 + 0], rmax0);
            float mnew1 = fmaxf(m_i[mi * 2 + 1], rmax1);
            float corr0 = ex2(m_i[mi * 2 + 0] - mnew0);
            float corr1 = ex2(m_i[mi * 2 + 1] - mnew1);
            m_i[mi * 2 + 0] = mnew0; m_i[mi * 2 + 1] = mnew1;

            float rsum0 = 0.f, rsum1 = 0.f;
            const int prow = (wrow + mi * 16 + lr) * 68;
#pragma unroll
            for (int nb = 0; nb < 8; nb++) {
                float p0 = ex2(sc[mi][nb][0] - mnew0);
                float p1 = ex2(sc[mi][nb][1] - mnew0);
                float p2 = ex2(sc[mi][nb][2] - mnew1);
                float p3 = ex2(sc[mi][nb][3] - mnew1);
                rsum0 += p0 + p1;
                rsum1 += p2 + p3;
                uint2 w0, w1;
                w0.x = f2tf32(p0); w0.y = f2tf32(p1);
                w1.x = f2tf32(p2); w1.y = f2tf32(p3);
                *(uint2*)&Ps[prow + nb * 8 + 2 * lc] = w0;
                *(uint2*)&Ps[prow + 8 * 68 + nb * 8 + 2 * lc] = w1;
            }
#pragma unroll
            for (int off = 1; off < 4; off <<= 1) {
                rsum0 += __shfl_xor_sync(0xffffffffu, rsum0, off);
                rsum1 += __shfl_xor_sync(0xffffffffu, rsum1, off);
            }
            l_i[mi * 2 + 0] = l_i[mi * 2 + 0] * corr0 + rsum0;
            l_i[mi * 2 + 1] = l_i[mi * 2 + 1] * corr1 + rsum1;
#pragma unroll
            for (int nb = 0; nb < 8; nb++) {
                o[mi][nb][0] *= corr0; o[mi][nb][1] *= corr0;
                o[mi][nb][2] *= corr1; o[mi][nb][3] *= corr1;
            }
        }
        __syncwarp();         // P rows are warp-private

        CP_WAIT1();           // V(t) complete (K(t+1) may pend)
        __syncthreads();

        // O += P V
#pragma unroll
        for (int ks = 0; ks < 8; ks++) {
            const int k0 = ks * 8;
            uint32_t a[2][4];
#pragma unroll
            for (int mi = 0; mi < 2; mi++) {
                int row = wrow + mi * 16 + lr;
                a[mi][0] = Ps[row * 68 + k0 + lc];
                a[mi][1] = Ps[(row + 8) * 68 + k0 + lc];
                a[mi][2] = Ps[row * 68 + k0 + lc + 4];
                a[mi][3] = Ps[(row + 8) * 68 + k0 + lc + 4];
            }
#pragma unroll
            for (int nb = 0; nb < 8; nb++) {
                uint32_t b[2];
                b[0] = Vs[(k0 + lc) * 72 + nb * 8 + lr];
                b[1] = Vs[(k0 + lc + 4) * 72 + nb * 8 + lr];
                MMA_TF32(o[0][nb], a[0], b);
                MMA_TF32(o[1][nb], a[1], b);
            }
        }
        __syncthreads();      // all warps done reading Vs
        if (t + 1 < ntiles) issueV(t + 1);
        CP_COMMIT();
    }

    // epilogue
    const int b = bh >> 4;
    const int h = bh & 15;
#pragma unroll
    for (int mi = 0; mi < 2; mi++) {
        const float inv0 = 1.0f / l_i[mi * 2 + 0];
        const float inv1 = 1.0f / l_i[mi * 2 + 1];
        const int row0 = m0 + wrow + mi * 16 + lr;
#pragma unroll
        for (int nb = 0; nb < 8; nb++) {
            int d = h * DKK + nb * 8 + 2 * lc;
            float2 v0, v1;
            v0.x = o[mi][nb][0] * inv0; v0.y = o[mi][nb][1] * inv0;
            v1.x = o[mi][nb][2] * inv1; v1.y = o[mi][nb][3] * inv1;
            *(float2*)&out[((size_t)(b * SS + row0)) * DD + d] = v0;
            *(float2*)&out[((size_t)(b * SS + row0 + 8)) * DD + d] = v1;
        }
    }
}

// ---------------------------------------------------------------------------
extern "C" void kernel_launch(void* const* d_in, const int* in_sizes, int n_in,
                              void* d_out, int out_size)
{
    const float* q  = (const float*)d_in[0];
    const float* v  = (const float*)d_in[1];
    const float* k  = (const float*)d_in[2];
    // d_in[3] = attn_mask (causal, known analytically) — unused
    const float* Wq = (const float*)d_in[4];
    const float* bq = (const float*)d_in[5];
    const float* Wk = (const float*)d_in[6];
    const float* bk = (const float*)d_in[7];
    const float* Wv = (const float*)d_in[8];
    const float* bv = (const float*)d_in[9];
    float* out = (float*)d_out;

    cvt_prepass<<<dim3(2048, 6), 256>>>(q, k, v, Wq, Wk, Wv);

    const int gemmSmem = (2 * 128 * 36 + 2 * 128 * 36) * sizeof(uint32_t);   // 73728
    cudaFuncSetAttribute(qkv_gemm_tf32, cudaFuncAttributeMaxDynamicSharedMemorySize, gemmSmem);
    dim3 gGemm(MTOT / 128, DD / 128, 3);
    qkv_gemm_tf32<<<gGemm, 256, gemmSmem>>>(bq, bk, bv);

    const int attnSmem = (128 * 68 + 64 * 68 + 64 * 72 + 128 * 68) * sizeof(uint32_t);
    cudaFuncSetAttribute(flash_attn_tc, cudaFuncAttributeMaxDynamicSharedMemorySize, attnSmem);
    dim3 gAttn(SS / 128, BB * HH);
    flash_attn_tc<<<gAttn, 128, attnSmem>>>(out);
}

// round 7
// speedup vs baseline: 4.7441x; 1.0812x over previous
#include <cuda_runtime.h>
#include <cuda_bf16.h>
#include <cstdint>

#define BB 4
#define SS 2048
#define DD 1024
#define HH 16
#define DKK 64
#define MTOT (BB*SS)          // 8192

// log2(e) / sqrt(64) folded into Q projection
#define QSCALE 0.18033688011112042f

// Scratch (all values stored as tf32-rna-rounded fp32 bit patterns)
__device__ float g_Q[(size_t)MTOT * DD];
__device__ float g_K[(size_t)MTOT * DD];
__device__ float g_V[(size_t)MTOT * DD];
__device__ float g_X[3][(size_t)MTOT * DD];   // pre-rounded q,k,v inputs
__device__ float g_W[3][(size_t)DD * DD];     // pre-rounded Wq,Wk,Wv

__device__ __forceinline__ uint32_t f2tf32(float f) {
    uint32_t u;
    asm("cvt.rna.tf32.f32 %0, %1;" : "=r"(u) : "f"(f));
    return u;
}
__device__ __forceinline__ float ex2(float x) {
    float y;
    asm("ex2.approx.ftz.f32 %0, %1;" : "=f"(y) : "f"(x));
    return y;
}
__device__ __forceinline__ uint32_t saddr(const void* p) {
    return (uint32_t)__cvta_generic_to_shared(p);
}
__device__ __forceinline__ void cp16(uint32_t s, const void* g) {
    asm volatile("cp.async.cg.shared.global [%0], [%1], 16;" :: "r"(s), "l"(g));
}
#define CP_COMMIT() asm volatile("cp.async.commit_group;")
#define CP_WAIT1()  asm volatile("cp.async.wait_group 1;")

#define MMA_TF32(d, a, b)                                                     \
    asm volatile("mma.sync.aligned.m16n8k8.row.col.f32.tf32.tf32.f32 "        \
                 "{%0,%1,%2,%3}, {%4,%5,%6,%7}, {%8,%9}, {%0,%1,%2,%3};"      \
                 : "+f"(d[0]), "+f"(d[1]), "+f"(d[2]), "+f"(d[3])             \
                 : "r"(a[0]), "r"(a[1]), "r"(a[2]), "r"(a[3]),                \
                   "r"(b[0]), "r"(b[1]));

// ---------------------------------------------------------------------------
// Pre-round pass: fp32 -> tf32(rna) bit patterns.
// ---------------------------------------------------------------------------
__global__ void cvt_prepass(const float* __restrict__ q,
                            const float* __restrict__ k,
                            const float* __restrict__ v,
                            const float* __restrict__ Wq,
                            const float* __restrict__ Wk,
                            const float* __restrict__ Wv)
{
    const float* src; float* dst; size_t n;
    switch (blockIdx.y) {
        case 0: src = q;  dst = g_X[0]; n = (size_t)MTOT * DD; break;
        case 1: src = k;  dst = g_X[1]; n = (size_t)MTOT * DD; break;
        case 2: src = v;  dst = g_X[2]; n = (size_t)MTOT * DD; break;
        case 3: src = Wq; dst = g_W[0]; n = (size_t)DD * DD;   break;
        case 4: src = Wk; dst = g_W[1]; n = (size_t)DD * DD;   break;
        default: src = Wv; dst = g_W[2]; n = (size_t)DD * DD;  break;
    }
    const float4* s4 = (const float4*)src;
    float4* d4 = (float4*)dst;
    size_t n4 = n >> 2;
    size_t stride = (size_t)gridDim.x * blockDim.x;
    for (size_t i = (size_t)blockIdx.x * blockDim.x + threadIdx.x; i < n4; i += stride) {
        float4 val = s4[i];
        float4 o;
        o.x = __uint_as_float(f2tf32(val.x));
        o.y = __uint_as_float(f2tf32(val.y));
        o.z = __uint_as_float(f2tf32(val.z));
        o.w = __uint_as_float(f2tf32(val.w));
        d4[i] = o;
    }
}

// ---------------------------------------------------------------------------
// QKV projection, tf32 mma.sync, 3-stage cp.async ring, XOR-swizzled smem.
// Tile 128x128, K-chunk 32, 8 warps (2m x 4n), warp tile 64x32.
// smem word layout: pos(r, c) = r*32 + (c ^ (4*(r&7)))  -- conflict-free for
// both cp16 row fills and m16n8k8 fragment reads (bank = c ^ 4*lr pattern).
// ---------------------------------------------------------------------------
#define GSTAGE 8192   // words per stage: X 128x32 + W 128x32

__global__ __launch_bounds__(256, 2)
void qkv_gemm_tf32(const float* __restrict__ bq,
                   const float* __restrict__ bk,
                   const float* __restrict__ bv)
{
    extern __shared__ uint32_t gsm[];

    const int z = blockIdx.z;
    const float* X = g_X[z];
    const float* W = g_W[z];
    const float* bias = (z == 0) ? bq : (z == 1) ? bk : bv;
    float* out = (z == 0) ? g_Q : (z == 1) ? g_K : g_V;
    const float oscale = (z == 0) ? QSCALE : 1.f;

    const int m0 = blockIdx.x * 128;
    const int n0 = blockIdx.y * 128;
    const int tid  = threadIdx.x;
    const int warp = tid >> 5;
    const int lane = tid & 31;
    const int wm = warp >> 2;       // 0..1 -> 64 rows
    const int wn = warp & 3;        // 0..3 -> 32 cols
    const int lr = lane >> 2;       // 0..7
    const int lc = lane & 3;        // 0..3
    const int xr = lr << 2;         // fragment-read XOR term (row&7 == lr)

    float acc[4][4][4];
#pragma unroll
    for (int mi = 0; mi < 4; mi++)
#pragma unroll
        for (int ni = 0; ni < 4; ni++)
#pragma unroll
            for (int c = 0; c < 4; c++) acc[mi][ni][c] = 0.f;

    auto fill = [&](int it) {
        const int s = it % 3;
        const int kc = it * 32;
        uint32_t* Xs = gsm + s * GSTAGE;
        uint32_t* Ws = Xs + 4096;
#pragma unroll
        for (int e = tid; e < 1024; e += 256) {
            int r  = e >> 3;
            int c4 = e & 7;
            int pos = r * 32 + ((c4 * 4) ^ ((r & 7) << 2));
            cp16(saddr(&Xs[pos]), &X[(size_t)(m0 + r) * DD + kc + c4 * 4]);
            cp16(saddr(&Ws[pos]), &W[(size_t)(n0 + r) * DD + kc + c4 * 4]);
        }
    };

    fill(0); CP_COMMIT();
    fill(1); CP_COMMIT();

    for (int it = 0; it < 32; it++) {
        CP_WAIT1();                 // fill(it) complete; fill(it+1) may pend
        __syncthreads();

        const uint32_t* Xc = gsm + (it % 3) * GSTAGE;
        const uint32_t* Wc = Xc + 4096;
#pragma unroll
        for (int ks = 0; ks < 4; ks++) {
            const int k0 = ks * 8;
            const int i0 = (k0 + lc) ^ xr;
            const int i1 = (k0 + lc + 4) ^ xr;
            uint32_t a[4][4];
#pragma unroll
            for (int mi = 0; mi < 4; mi++) {
                int row = wm * 64 + mi * 16 + lr;
                a[mi][0] = Xc[row * 32 + i0];
                a[mi][1] = Xc[(row + 8) * 32 + i0];
                a[mi][2] = Xc[row * 32 + i1];
                a[mi][3] = Xc[(row + 8) * 32 + i1];
            }
            uint32_t b[4][2];
#pragma unroll
            for (int ni = 0; ni < 4; ni++) {
                int col = wn * 32 + ni * 8 + lr;
                b[ni][0] = Wc[col * 32 + i0];
                b[ni][1] = Wc[col * 32 + i1];
            }
#pragma unroll
            for (int mi = 0; mi < 4; mi++)
#pragma unroll
                for (int ni = 0; ni < 4; ni++)
                    MMA_TF32(acc[mi][ni], a[mi], b[ni]);
        }
        __syncthreads();            // all warps done with stage it%3
        if (it + 2 < 32) fill(it + 2);
        CP_COMMIT();                // uniform group accounting
    }

    // epilogue: bias, scale, tf32-round, scatter head-major
#pragma unroll
    for (int mi = 0; mi < 4; mi++) {
#pragma unroll
        for (int ni = 0; ni < 4; ni++) {
            int m = m0 + wm * 64 + mi * 16 + lr;
            int n = n0 + wn * 32 + ni * 8 + 2 * lc;
            float b0 = __ldg(&bias[n]), b1 = __ldg(&bias[n + 1]);
            int h = n >> 6, d = n & 63;
#pragma unroll
            for (int half = 0; half < 2; half++) {
                int mm = m + half * 8;
                int b_ = mm >> 11, s = mm & 2047;
                float2 val;
                val.x = __uint_as_float(f2tf32((acc[mi][ni][half * 2 + 0] + b0) * oscale));
                val.y = __uint_as_float(f2tf32((acc[mi][ni][half * 2 + 1] + b1) * oscale));
                *(float2*)&out[(((size_t)(b_ * HH + h) * SS) + s) * DKK + d] = val;
            }
        }
    }
}

// ---------------------------------------------------------------------------
// Causal flash attention, tf32 MMA, split-issue cp.async pipeline (R5).
// ---------------------------------------------------------------------------
__global__ __launch_bounds__(128)
void flash_attn_tc(float* __restrict__ out)
{
    extern __shared__ uint32_t smu[];
    uint32_t* Qs = smu;                 // 128*68
    uint32_t* Ks = Qs + 128 * 68;       // 64*68
    uint32_t* Vs = Ks + 64 * 68;        // 64*72
    uint32_t* Ps = Vs + 64 * 72;        // 128*68

    const int bh = blockIdx.y;
    const int qt = blockIdx.x;
    const int m0 = qt * 128;

    const float* Qp = g_Q + (size_t)bh * SS * DKK;
    const float* Kp = g_K + (size_t)bh * SS * DKK;
    const float* Vp = g_V + (size_t)bh * SS * DKK;

    const int tid  = threadIdx.x;
    const int warp = tid >> 5;
    const int lane = tid & 31;
    const int lr = lane >> 2;
    const int lc = lane & 3;
    const int wrow = warp * 32;

    auto issueK = [&](int t) {
        const int n0 = t * 64;
#pragma unroll
        for (int e = tid; e < 1024; e += 128) {
            int r = e >> 4, c4 = e & 15;
            cp16(saddr(&Ks[r * 68 + c4 * 4]), &Kp[(size_t)(n0 + r) * DKK + c4 * 4]);
        }
    };
    auto issueV = [&](int t) {
        const int n0 = t * 64;
#pragma unroll
        for (int e = tid; e < 1024; e += 128) {
            int r = e >> 4, c4 = e & 15;
            cp16(saddr(&Vs[r * 72 + c4 * 4]), &Vp[(size_t)(n0 + r) * DKK + c4 * 4]);
        }
    };

#pragma unroll
    for (int e = tid; e < 2048; e += 128) {
        int r = e >> 4, c4 = e & 15;
        cp16(saddr(&Qs[r * 68 + c4 * 4]), &Qp[(size_t)(m0 + r) * DKK + c4 * 4]);
    }
    CP_COMMIT();
    issueK(0); CP_COMMIT();
    issueV(0); CP_COMMIT();

    float m_i[4], l_i[4];
    float o[2][8][4];
#pragma unroll
    for (int i = 0; i < 4; i++) { m_i[i] = -1e30f; l_i[i] = 0.f; }
#pragma unroll
    for (int mi = 0; mi < 2; mi++)
#pragma unroll
        for (int nb = 0; nb < 8; nb++)
#pragma unroll
            for (int c = 0; c < 4; c++) o[mi][nb][c] = 0.f;

    const int ntiles = 2 * qt + 2;
    for (int t = 0; t < ntiles; t++) {
        const int n0 = t * 64;

        CP_WAIT1();
        __syncthreads();

        float sc[2][8][4];
#pragma unroll
        for (int mi = 0; mi < 2; mi++)
#pragma unroll
            for (int nb = 0; nb < 8; nb++)
#pragma unroll
                for (int c = 0; c < 4; c++) sc[mi][nb][c] = 0.f;

#pragma unroll
        for (int ks = 0; ks < 8; ks++) {
            const int k0 = ks * 8;
            uint32_t a[2][4];
#pragma unroll
            for (int mi = 0; mi < 2; mi++) {
                int row = wrow + mi * 16 + lr;
                a[mi][0] = Qs[row * 68 + k0 + lc];
                a[mi][1] = Qs[(row + 8) * 68 + k0 + lc];
                a[mi][2] = Qs[row * 68 + k0 + lc + 4];
                a[mi][3] = Qs[(row + 8) * 68 + k0 + lc + 4];
            }
#pragma unroll
            for (int nb = 0; nb < 8; nb++) {
                uint32_t b[2];
                b[0] = Ks[(nb * 8 + lr) * 68 + k0 + lc];
                b[1] = Ks[(nb * 8 + lr) * 68 + k0 + lc + 4];
                MMA_TF32(sc[0][nb], a[0], b);
                MMA_TF32(sc[1][nb], a[1], b);
            }
        }
        __syncthreads();
        if (t + 1 < ntiles) issueK(t + 1);
        CP_COMMIT();

        if (t >= 2 * qt) {
#pragma unroll
            for (int mi = 0; mi < 2; mi++) {
                const int row0 = m0 + wrow + mi * 16 + lr;
                const int row1 = row0 + 8;
#pragma unroll
                for (int nb = 0; nb < 8; nb++) {
                    int col = n0 + nb * 8 + 2 * lc;
                    if (col > row0)     sc[mi][nb][0] = -1e30f;
                    if (col + 1 > row0) sc[mi][nb][1] = -1e30f;
                    if (col > row1)     sc[mi][nb][2] = -1e30f;
                    if (col + 1 > row1) sc[mi][nb][3] = -1e30f;
                }
            }
        }

#pragma unroll
        for (int mi = 0; mi < 2; mi++) {
            float rmax0 = -1e30f, rmax1 = -1e30f;
#pragma unroll
            for (int nb = 0; nb < 8; nb++) {
                rmax0 = fmaxf(rmax0, fmaxf(sc[mi][nb][0], sc[mi][nb][1]));
                rmax1 = fmaxf(rmax1, fmaxf(sc[mi][nb][2], sc[mi][nb][3]));
            }
#pragma unroll
            for (int off = 1; off < 4; off <<= 1) {
                rmax0 = fmaxf(rmax0, __shfl_xor_sync(0xffffffffu, rmax0, off));
                rmax1 = fmaxf(rmax1, __shfl_xor_sync(0xffffffffu, rmax1, off));
            }
            float mnew0 = fmaxf(m_i[mi * 2 + 0], rmax0);
            float mnew1 = fmaxf(m_i[mi * 2 + 1], rmax1);
            float corr0 = ex2(m_i[mi * 2 + 0] - mnew0);
            float corr1 = ex2(m_i[mi * 2 + 1] - mnew1);
            m_i[mi * 2 + 0] = mnew0; m_i[mi * 2 + 1] = mnew1;

            float rsum0 = 0.f, rsum1 = 0.f;
            const int prow = (wrow + mi * 16 + lr) * 68;
#pragma unroll
            for (int nb = 0; nb < 8; nb++) {
                float p0 = ex2(sc[mi][nb][0] - mnew0);
                float p1 = ex2(sc[mi][nb][1] - mnew0);
                float p2 = ex2(sc[mi][nb][2] - mnew1);
                float p3 = ex2(sc[mi][nb][3] - mnew1);
                rsum0 += p0 + p1;
                rsum1 += p2 + p3;
                uint2 w0, w1;
                w0.x = f2tf32(p0); w0.y = f2tf32(p1);
                w1.x = f2tf32(p2); w1.y = f2tf32(p3);
                *(uint2*)&Ps[prow + nb * 8 + 2 * lc] = w0;
                *(uint2*)&Ps[prow + 8 * 68 + nb * 8 + 2 * lc] = w1;
            }
#pragma unroll
            for (int off = 1; off < 4; off <<= 1) {
                rsum0 += __shfl_xor_sync(0xffffffffu, rsum0, off);
                rsum1 += __shfl_xor_sync(0xffffffffu, rsum1, off);
            }
            l_i[mi * 2 + 0] = l_i[mi * 2 + 0] * corr0 + rsum0;
            l_i[mi * 2 + 1] = l_i[mi * 2 + 1] * corr1 + rsum1;
#pragma unroll
            for (int nb = 0; nb < 8; nb++) {
                o[mi][nb][0] *= corr0; o[mi][nb][1] *= corr0;
                o[mi][nb][2] *= corr1; o[mi][nb][3] *= corr1;
            }
        }
        __syncwarp();

        CP_WAIT1();
        __syncthreads();

#pragma unroll
        for (int ks = 0; ks < 8; ks++) {
            const int k0 = ks * 8;
            uint32_t a[2][4];
#pragma unroll
            for (int mi = 0; mi < 2; mi++) {
                int row = wrow + mi * 16 + lr;
                a[mi][0] = Ps[row * 68 + k0 + lc];
                a[mi][1] = Ps[(row + 8) * 68 + k0 + lc];
                a[mi][2] = Ps[row * 68 + k0 + lc + 4];
                a[mi][3] = Ps[(row + 8) * 68 + k0 + lc + 4];
            }
#pragma unroll
            for (int nb = 0; nb < 8; nb++) {
                uint32_t b[2];
                b[0] = Vs[(k0 + lc) * 72 + nb * 8 + lr];
                b[1] = Vs[(k0 + lc + 4) * 72 + nb * 8 + lr];
                MMA_TF32(o[0][nb], a[0], b);
                MMA_TF32(o[1][nb], a[1], b);
            }
        }
        __syncthreads();
        if (t + 1 < ntiles) issueV(t + 1);
        CP_COMMIT();
    }

    const int b = bh >> 4;
    const int h = bh & 15;
#pragma unroll
    for (int mi = 0; mi < 2; mi++) {
        const float inv0 = 1.0f / l_i[mi * 2 + 0];
        const float inv1 = 1.0f / l_i[mi * 2 + 1];
        const int row0 = m0 + wrow + mi * 16 + lr;
#pragma unroll
        for (int nb = 0; nb < 8; nb++) {
            int d = h * DKK + nb * 8 + 2 * lc;
            float2 v0, v1;
            v0.x = o[mi][nb][0] * inv0; v0.y = o[mi][nb][1] * inv0;
            v1.x = o[mi][nb][2] * inv1; v1.y = o[mi][nb][3] * inv1;
            *(float2*)&out[((size_t)(b * SS + row0)) * DD + d] = v0;
            *(float2*)&out[((size_t)(b * SS + row0 + 8)) * DD + d] = v1;
        }
    }
}

// ---------------------------------------------------------------------------
extern "C" void kernel_launch(void* const* d_in, const int* in_sizes, int n_in,
                              void* d_out, int out_size)
{
    const float* q  = (const float*)d_in[0];
    const float* v  = (const float*)d_in[1];
    const float* k  = (const float*)d_in[2];
    // d_in[3] = attn_mask (causal, known analytically) — unused
    const float* Wq = (const float*)d_in[4];
    const float* bq = (const float*)d_in[5];
    const float* Wk = (const float*)d_in[6];
    const float* bk = (const float*)d_in[7];
    const float* Wv = (const float*)d_in[8];
    const float* bv = (const float*)d_in[9];
    float* out = (float*)d_out;

    cvt_prepass<<<dim3(2048, 6), 256>>>(q, k, v, Wq, Wk, Wv);

    const int gemmSmem = 3 * GSTAGE * sizeof(uint32_t);   // 98304
    cudaFuncSetAttribute(qkv_gemm_tf32, cudaFuncAttributeMaxDynamicSharedMemorySize, gemmSmem);
    dim3 gGemm(MTOT / 128, DD / 128, 3);   // 64 x 8 x 3
    qkv_gemm_tf32<<<gGemm, 256, gemmSmem>>>(bq, bk, bv);

    const int attnSmem = (128 * 68 + 64 * 68 + 64 * 72 + 128 * 68) * sizeof(uint32_t);
    cudaFuncSetAttribute(flash_attn_tc, cudaFuncAttributeMaxDynamicSharedMemorySize, attnSmem);
    dim3 gAttn(SS / 128, BB * HH);
    flash_attn_tc<<<gAttn, 128, attnSmem>>>(out);
}

// round 8
// speedup vs baseline: 8.3553x; 1.7612x over previous
#include <cuda_runtime.h>
#include <cuda_fp16.h>
#include <cstdint>

#define BB 4
#define SS 2048
#define DD 1024
#define HH 16
#define DKK 64
#define MTOT (BB*SS)          // 8192

// log2(e) / sqrt(64) folded into Q projection
#define QSCALE 0.18033688011112042f

// fp16 scratch. g_V is stored TRANSPOSED: [B*H][DK][S].
__device__ __half g_Q[(size_t)MTOT * DD];
__device__ __half g_K[(size_t)MTOT * DD];
__device__ __half g_V[(size_t)MTOT * DD];
__device__ __half g_X[3][(size_t)MTOT * DD];   // fp16 inputs q,k,v
__device__ __half g_W[3][(size_t)DD * DD];     // fp16 weights

__device__ __forceinline__ float ex2(float x) {
    float y;
    asm("ex2.approx.ftz.f32 %0, %1;" : "=f"(y) : "f"(x));
    return y;
}
__device__ __forceinline__ uint32_t saddr(const void* p) {
    return (uint32_t)__cvta_generic_to_shared(p);
}
__device__ __forceinline__ void cp16(uint32_t s, const void* g) {
    asm volatile("cp.async.cg.shared.global [%0], [%1], 16;" :: "r"(s), "l"(g));
}
#define CP_COMMIT() asm volatile("cp.async.commit_group;")
#define CP_WAIT1()  asm volatile("cp.async.wait_group 1;")

#define MMA_F16(d, a, b)                                                      \
    asm volatile("mma.sync.aligned.m16n8k16.row.col.f32.f16.f16.f32 "         \
                 "{%0,%1,%2,%3}, {%4,%5,%6,%7}, {%8,%9}, {%0,%1,%2,%3};"      \
                 : "+f"(d[0]), "+f"(d[1]), "+f"(d[2]), "+f"(d[3])             \
                 : "r"(a[0]), "r"(a[1]), "r"(a[2]), "r"(a[3]),                \
                   "r"(b[0]), "r"(b[1]));

// ---------------------------------------------------------------------------
// Pre-round pass: fp32 -> fp16 (rn).
// ---------------------------------------------------------------------------
__global__ void cvt_prepass(const float* __restrict__ q,
                            const float* __restrict__ k,
                            const float* __restrict__ v,
                            const float* __restrict__ Wq,
                            const float* __restrict__ Wk,
                            const float* __restrict__ Wv)
{
    const float* src; __half* dst; size_t n;
    switch (blockIdx.y) {
        case 0: src = q;  dst = g_X[0]; n = (size_t)MTOT * DD; break;
        case 1: src = k;  dst = g_X[1]; n = (size_t)MTOT * DD; break;
        case 2: src = v;  dst = g_X[2]; n = (size_t)MTOT * DD; break;
        case 3: src = Wq; dst = g_W[0]; n = (size_t)DD * DD;   break;
        case 4: src = Wk; dst = g_W[1]; n = (size_t)DD * DD;   break;
        default: src = Wv; dst = g_W[2]; n = (size_t)DD * DD;  break;
    }
    const float4* s4 = (const float4*)src;
    size_t n4 = n >> 2;
    size_t stride = (size_t)gridDim.x * blockDim.x;
    for (size_t i = (size_t)blockIdx.x * blockDim.x + threadIdx.x; i < n4; i += stride) {
        float4 val = s4[i];
        __half2 lo = __floats2half2_rn(val.x, val.y);
        __half2 hi = __floats2half2_rn(val.z, val.w);
        uint2 o;
        o.x = *(uint32_t*)&lo;
        o.y = *(uint32_t*)&hi;
        *(uint2*)&dst[i * 4] = o;
    }
}

// ---------------------------------------------------------------------------
// QKV projection, fp16 mma.sync m16n8k16, 3-stage cp.async ring.
// Tile 128x128, K-chunk 64 (32 half2-words/row), 8 warps (2m x 4n).
// smem word layout: pos(r, w) = r*32 + (w ^ (4*(r&7))) -- conflict-free.
// V output stored transposed [bh][d][s].
// ---------------------------------------------------------------------------
#define GSTAGE 8192   // words per stage: X 128x32 + W 128x32 (half2 words)

__global__ __launch_bounds__(256, 2)
void qkv_gemm_f16(const float* __restrict__ bq,
                  const float* __restrict__ bk,
                  const float* __restrict__ bv)
{
    extern __shared__ uint32_t gsm[];

    const int z = blockIdx.z;
    const __half* X = g_X[z];
    const __half* W = g_W[z];
    const float* bias = (z == 0) ? bq : (z == 1) ? bk : bv;
    const float oscale = (z == 0) ? QSCALE : 1.f;

    const int m0 = blockIdx.x * 128;
    const int n0 = blockIdx.y * 128;
    const int tid  = threadIdx.x;
    const int warp = tid >> 5;
    const int lane = tid & 31;
    const int wm = warp >> 2;
    const int wn = warp & 3;
    const int lr = lane >> 2;
    const int lc = lane & 3;
    const int xr = lr << 2;

    float acc[4][4][4];
#pragma unroll
    for (int mi = 0; mi < 4; mi++)
#pragma unroll
        for (int ni = 0; ni < 4; ni++)
#pragma unroll
            for (int c = 0; c < 4; c++) acc[mi][ni][c] = 0.f;

    auto fill = [&](int it) {
        const int s = it % 3;
        const int kc = it * 64;          // halves
        uint32_t* Xs = gsm + s * GSTAGE;
        uint32_t* Ws = Xs + 4096;
#pragma unroll
        for (int e = tid; e < 1024; e += 256) {
            int r  = e >> 3;
            int c4 = e & 7;
            int pos = r * 32 + ((c4 * 4) ^ ((r & 7) << 2));
            cp16(saddr(&Xs[pos]), &X[(size_t)(m0 + r) * DD + kc + c4 * 8]);
            cp16(saddr(&Ws[pos]), &W[(size_t)(n0 + r) * DD + kc + c4 * 8]);
        }
    };

    fill(0); CP_COMMIT();
    fill(1); CP_COMMIT();

    for (int it = 0; it < 16; it++) {
        CP_WAIT1();
        __syncthreads();

        const uint32_t* Xc = gsm + (it % 3) * GSTAGE;
        const uint32_t* Wc = Xc + 4096;
#pragma unroll
        for (int ks = 0; ks < 4; ks++) {
            const int i0 = (8 * ks + lc) ^ xr;
            const int i1 = i0 ^ 4;
            uint32_t a[4][4];
#pragma unroll
            for (int mi = 0; mi < 4; mi++) {
                int row = wm * 64 + mi * 16 + lr;
                a[mi][0] = Xc[row * 32 + i0];
                a[mi][1] = Xc[(row + 8) * 32 + i0];
                a[mi][2] = Xc[row * 32 + i1];
                a[mi][3] = Xc[(row + 8) * 32 + i1];
            }
            uint32_t b[4][2];
#pragma unroll
            for (int ni = 0; ni < 4; ni++) {
                int col = wn * 32 + ni * 8 + lr;
                b[ni][0] = Wc[col * 32 + i0];
                b[ni][1] = Wc[col * 32 + i1];
            }
#pragma unroll
            for (int mi = 0; mi < 4; mi++)
#pragma unroll
                for (int ni = 0; ni < 4; ni++)
                    MMA_F16(acc[mi][ni], a[mi], b[ni]);
        }
        __syncthreads();
        if (it + 2 < 16) fill(it + 2);
        CP_COMMIT();
    }

    // epilogue: bias, scale, fp16-round; Q/K head-major, V transposed
#pragma unroll
    for (int mi = 0; mi < 4; mi++) {
#pragma unroll
        for (int ni = 0; ni < 4; ni++) {
            int m = m0 + wm * 64 + mi * 16 + lr;
            int n = n0 + wn * 32 + ni * 8 + 2 * lc;
            float b0 = __ldg(&bias[n]), b1 = __ldg(&bias[n + 1]);
            int h = n >> 6, d = n & 63;
#pragma unroll
            for (int half_ = 0; half_ < 2; half_++) {
                int mm = m + half_ * 8;
                int b_ = mm >> 11, s_ = mm & 2047;
                int bh = b_ * HH + h;
                float v0 = (acc[mi][ni][half_ * 2 + 0] + b0) * oscale;
                float v1 = (acc[mi][ni][half_ * 2 + 1] + b1) * oscale;
                if (z == 2) {
                    __half* vt = g_V + ((size_t)bh * DKK + d) * SS + s_;
                    vt[0]  = __float2half_rn(v0);
                    vt[SS] = __float2half_rn(v1);
                } else {
                    __half* dst = (z == 0) ? g_Q : g_K;
                    __half2 pk = __floats2half2_rn(v0, v1);
                    *(__half2*)&dst[((size_t)bh * SS + s_) * DKK + d] = pk;
                }
            }
        }
    }
}

// ---------------------------------------------------------------------------
// Causal flash attention, fp16 m16n8k16. BM=128, 8 warps x 16-row tiles.
// Q/K/P/Vt all in XOR-swizzled 32-word rows; V pre-transposed so PV B-frags
// read contiguous half2 exactly like K. Split-issue cp.async pipeline.
// smem: 48 KB -> 2 CTAs/SM (reg-limited), 16 warps/SM.
// ---------------------------------------------------------------------------
__global__ __launch_bounds__(256, 2)
void flash_attn_f16(float* __restrict__ out)
{
    extern __shared__ uint32_t smu[];
    uint32_t* Qs = smu;                 // 128*32 words
    uint32_t* Ks = Qs + 128 * 32;       // 64*32
    uint32_t* Vs = Ks + 64 * 32;        // 64*32 (Vt tile: row=d, col=seq)
    uint32_t* Ps = Vs + 64 * 32;        // 128*32

    const int bh = blockIdx.y;
    const int qt = blockIdx.x;
    const int m0 = qt * 128;

    const __half* Qp = g_Q + (size_t)bh * SS * DKK;
    const __half* Kp = g_K + (size_t)bh * SS * DKK;
    const __half* Vp = g_V + (size_t)bh * DKK * SS;   // transposed

    const int tid  = threadIdx.x;
    const int warp = tid >> 5;
    const int lane = tid & 31;
    const int lr = lane >> 2;
    const int lc = lane & 3;
    const int xr = lr << 2;
    const int wrow = warp * 16;

    auto issueK = [&](int t) {
        const int n0 = t * 64;
#pragma unroll
        for (int e = tid; e < 512; e += 256) {
            int r = e >> 3, c4 = e & 7;
            int pos = r * 32 + ((c4 * 4) ^ ((r & 7) << 2));
            cp16(saddr(&Ks[pos]), &Kp[(size_t)(n0 + r) * DKK + c4 * 8]);
        }
    };
    auto issueV = [&](int t) {
        const int n0 = t * 64;
#pragma unroll
        for (int e = tid; e < 512; e += 256) {
            int r = e >> 3, c4 = e & 7;      // r = d row of Vt
            int pos = r * 32 + ((c4 * 4) ^ ((r & 7) << 2));
            cp16(saddr(&Vs[pos]), &Vp[(size_t)r * SS + n0 + c4 * 8]);
        }
    };

    // prologue: Q group, K(0), V(0)
#pragma unroll
    for (int e = tid; e < 1024; e += 256) {
        int r = e >> 3, c4 = e & 7;
        int pos = r * 32 + ((c4 * 4) ^ ((r & 7) << 2));
        cp16(saddr(&Qs[pos]), &Qp[(size_t)(m0 + r) * DKK + c4 * 8]);
    }
    CP_COMMIT();
    issueK(0); CP_COMMIT();
    issueV(0); CP_COMMIT();

    float m_i[2], l_i[2], o[8][4];
    m_i[0] = m_i[1] = -1e30f;
    l_i[0] = l_i[1] = 0.f;
#pragma unroll
    for (int nb = 0; nb < 8; nb++)
#pragma unroll
        for (int c = 0; c < 4; c++) o[nb][c] = 0.f;

    const int ntiles = 2 * qt + 2;
    for (int t = 0; t < ntiles; t++) {
        const int n0 = t * 64;

        CP_WAIT1();            // Q + K(t) ready
        __syncthreads();

        // S = Q K^T (warp: 16x64)
        float sc[8][4];
#pragma unroll
        for (int nb = 0; nb < 8; nb++)
#pragma unroll
            for (int c = 0; c < 4; c++) sc[nb][c] = 0.f;

#pragma unroll
        for (int ks = 0; ks < 4; ks++) {
            const int i0 = (8 * ks + lc) ^ xr;
            const int i1 = i0 ^ 4;
            uint32_t a[4];
            a[0] = Qs[(wrow + lr) * 32 + i0];
            a[1] = Qs[(wrow + lr + 8) * 32 + i0];
            a[2] = Qs[(wrow + lr) * 32 + i1];
            a[3] = Qs[(wrow + lr + 8) * 32 + i1];
#pragma unroll
            for (int nb = 0; nb < 8; nb++) {
                uint32_t b[2];
                b[0] = Ks[(nb * 8 + lr) * 32 + i0];
                b[1] = Ks[(nb * 8 + lr) * 32 + i1];
                MMA_F16(sc[nb], a, b);
            }
        }
        __syncthreads();
        if (t + 1 < ntiles) issueK(t + 1);
        CP_COMMIT();

        // causal mask (diagonal tiles only)
        if (t >= 2 * qt) {
            const int row0 = m0 + wrow + lr;
            const int row1 = row0 + 8;
#pragma unroll
            for (int nb = 0; nb < 8; nb++) {
                int col = n0 + nb * 8 + 2 * lc;
                if (col > row0)     sc[nb][0] = -1e30f;
                if (col + 1 > row0) sc[nb][1] = -1e30f;
                if (col > row1)     sc[nb][2] = -1e30f;
                if (col + 1 > row1) sc[nb][3] = -1e30f;
            }
        }

        // online softmax (log2 domain)
        float rmax0 = -1e30f, rmax1 = -1e30f;
#pragma unroll
        for (int nb = 0; nb < 8; nb++) {
            rmax0 = fmaxf(rmax0, fmaxf(sc[nb][0], sc[nb][1]));
            rmax1 = fmaxf(rmax1, fmaxf(sc[nb][2], sc[nb][3]));
        }
#pragma unroll
        for (int off = 1; off < 4; off <<= 1) {
            rmax0 = fmaxf(rmax0, __shfl_xor_sync(0xffffffffu, rmax0, off));
            rmax1 = fmaxf(rmax1, __shfl_xor_sync(0xffffffffu, rmax1, off));
        }
        float mnew0 = fmaxf(m_i[0], rmax0);
        float mnew1 = fmaxf(m_i[1], rmax1);
        float corr0 = ex2(m_i[0] - mnew0);
        float corr1 = ex2(m_i[1] - mnew1);
        m_i[0] = mnew0; m_i[1] = mnew1;

        float rsum0 = 0.f, rsum1 = 0.f;
        const int prow0 = (wrow + lr) * 32;
        const int prow1 = (wrow + lr + 8) * 32;
#pragma unroll
        for (int nb = 0; nb < 8; nb++) {
            float p0 = ex2(sc[nb][0] - mnew0);
            float p1 = ex2(sc[nb][1] - mnew0);
            float p2 = ex2(sc[nb][2] - mnew1);
            float p3 = ex2(sc[nb][3] - mnew1);
            rsum0 += p0 + p1;
            rsum1 += p2 + p3;
            __half2 w0 = __floats2half2_rn(p0, p1);
            __half2 w1 = __floats2half2_rn(p2, p3);
            int wi = (4 * nb + lc) ^ xr;
            Ps[prow0 + wi] = *(uint32_t*)&w0;
            Ps[prow1 + wi] = *(uint32_t*)&w1;
        }
#pragma unroll
        for (int off = 1; off < 4; off <<= 1) {
            rsum0 += __shfl_xor_sync(0xffffffffu, rsum0, off);
            rsum1 += __shfl_xor_sync(0xffffffffu, rsum1, off);
        }
        l_i[0] = l_i[0] * corr0 + rsum0;
        l_i[1] = l_i[1] * corr1 + rsum1;
#pragma unroll
        for (int nb = 0; nb < 8; nb++) {
            o[nb][0] *= corr0; o[nb][1] *= corr0;
            o[nb][2] *= corr1; o[nb][3] *= corr1;
        }
        __syncwarp();           // P rows warp-private

        CP_WAIT1();             // V(t) ready
        __syncthreads();

        // O += P V  (A=P rows, B=Vt rows exactly like K)
#pragma unroll
        for (int ks = 0; ks < 4; ks++) {
            const int i0 = (8 * ks + lc) ^ xr;
            const int i1 = i0 ^ 4;
            uint32_t a[4];
            a[0] = Ps[(wrow + lr) * 32 + i0];
            a[1] = Ps[(wrow + lr + 8) * 32 + i0];
            a[2] = Ps[(wrow + lr) * 32 + i1];
            a[3] = Ps[(wrow + lr + 8) * 32 + i1];
#pragma unroll
            for (int nb = 0; nb < 8; nb++) {
                uint32_t b[2];
                b[0] = Vs[(nb * 8 + lr) * 32 + i0];
                b[1] = Vs[(nb * 8 + lr) * 32 + i1];
                MMA_F16(o[nb], a, b);
            }
        }
        __syncthreads();
        if (t + 1 < ntiles) issueV(t + 1);
        CP_COMMIT();
    }

    // epilogue
    const int b = bh >> 4;
    const int h = bh & 15;
    const float inv0 = 1.0f / l_i[0];
    const float inv1 = 1.0f / l_i[1];
    const int row0 = m0 + wrow + lr;
#pragma unroll
    for (int nb = 0; nb < 8; nb++) {
        int d = h * DKK + nb * 8 + 2 * lc;
        float2 v0, v1;
        v0.x = o[nb][0] * inv0; v0.y = o[nb][1] * inv0;
        v1.x = o[nb][2] * inv1; v1.y = o[nb][3] * inv1;
        *(float2*)&out[((size_t)(b * SS + row0)) * DD + d] = v0;
        *(float2*)&out[((size_t)(b * SS + row0 + 8)) * DD + d] = v1;
    }
}

// ---------------------------------------------------------------------------
extern "C" void kernel_launch(void* const* d_in, const int* in_sizes, int n_in,
                              void* d_out, int out_size)
{
    const float* q  = (const float*)d_in[0];
    const float* v  = (const float*)d_in[1];
    const float* k  = (const float*)d_in[2];
    // d_in[3] = attn_mask (causal, known analytically) — unused
    const float* Wq = (const float*)d_in[4];
    const float* bq = (const float*)d_in[5];
    const float* Wk = (const float*)d_in[6];
    const float* bk = (const float*)d_in[7];
    const float* Wv = (const float*)d_in[8];
    const float* bv = (const float*)d_in[9];
    float* out = (float*)d_out;

    cvt_prepass<<<dim3(2048, 6), 256>>>(q, k, v, Wq, Wk, Wv);

    const int gemmSmem = 3 * GSTAGE * sizeof(uint32_t);   // 98304
    cudaFuncSetAttribute(qkv_gemm_f16, cudaFuncAttributeMaxDynamicSharedMemorySize, gemmSmem);
    dim3 gGemm(MTOT / 128, DD / 128, 3);   // 64 x 8 x 3
    qkv_gemm_f16<<<gGemm, 256, gemmSmem>>>(bq, bk, bv);

    const int attnSmem = (128 * 32 + 64 * 32 + 64 * 32 + 128 * 32) * sizeof(uint32_t);  // 49152
    cudaFuncSetAttribute(flash_attn_f16, cudaFuncAttributeMaxDynamicSharedMemorySize, attnSmem);
    dim3 gAttn(SS / 128, BB * HH);
    flash_attn_f16<<<gAttn, 256, attnSmem>>>(out);
}

// round 9
// speedup vs baseline: 8.9340x; 1.0693x over previous
#include <cuda_runtime.h>
#include <cuda_fp16.h>
#include <cstdint>

#define BB 4
#define SS 2048
#define DD 1024
#define HH 16
#define DKK 64
#define MTOT (BB*SS)          // 8192

// log2(e) / sqrt(64) folded into Q projection
#define QSCALE 0.18033688011112042f

// fp16 scratch. g_V is stored TRANSPOSED: [B*H][DK][S].
__device__ __half g_Q[(size_t)MTOT * DD];
__device__ __half g_K[(size_t)MTOT * DD];
__device__ __half g_V[(size_t)MTOT * DD];
__device__ __half g_X[3][(size_t)MTOT * DD];   // fp16 inputs q,k,v
__device__ __half g_W[3][(size_t)DD * DD];     // fp16 weights

__device__ __forceinline__ float ex2(float x) {
    float y;
    asm("ex2.approx.ftz.f32 %0, %1;" : "=f"(y) : "f"(x));
    return y;
}
__device__ __forceinline__ uint32_t saddr(const void* p) {
    return (uint32_t)__cvta_generic_to_shared(p);
}
__device__ __forceinline__ void cp16(uint32_t s, const void* g) {
    asm volatile("cp.async.cg.shared.global [%0], [%1], 16;" :: "r"(s), "l"(g));
}
#define CP_COMMIT() asm volatile("cp.async.commit_group;")
#define CP_WAIT1()  asm volatile("cp.async.wait_group 1;")
#define CP_WAIT2()  asm volatile("cp.async.wait_group 2;")

#define MMA_F16(d, a, b)                                                      \
    asm volatile("mma.sync.aligned.m16n8k16.row.col.f32.f16.f16.f32 "         \
                 "{%0,%1,%2,%3}, {%4,%5,%6,%7}, {%8,%9}, {%0,%1,%2,%3};"      \
                 : "+f"(d[0]), "+f"(d[1]), "+f"(d[2]), "+f"(d[3])             \
                 : "r"(a[0]), "r"(a[1]), "r"(a[2]), "r"(a[3]),                \
                   "r"(b[0]), "r"(b[1]));

__device__ __forceinline__ uint32_t packh2(float a, float b) {
    __half2 h = __floats2half2_rn(a, b);
    return *(uint32_t*)&h;
}

// ---------------------------------------------------------------------------
// Pre-round pass: fp32 -> fp16 (rn).
// ---------------------------------------------------------------------------
__global__ void cvt_prepass(const float* __restrict__ q,
                            const float* __restrict__ k,
                            const float* __restrict__ v,
                            const float* __restrict__ Wq,
                            const float* __restrict__ Wk,
                            const float* __restrict__ Wv)
{
    const float* src; __half* dst; size_t n;
    switch (blockIdx.y) {
        case 0: src = q;  dst = g_X[0]; n = (size_t)MTOT * DD; break;
        case 1: src = k;  dst = g_X[1]; n = (size_t)MTOT * DD; break;
        case 2: src = v;  dst = g_X[2]; n = (size_t)MTOT * DD; break;
        case 3: src = Wq; dst = g_W[0]; n = (size_t)DD * DD;   break;
        case 4: src = Wk; dst = g_W[1]; n = (size_t)DD * DD;   break;
        default: src = Wv; dst = g_W[2]; n = (size_t)DD * DD;  break;
    }
    const float4* s4 = (const float4*)src;
    size_t n4 = n >> 2;
    size_t stride = (size_t)gridDim.x * blockDim.x;
    for (size_t i = (size_t)blockIdx.x * blockDim.x + threadIdx.x; i < n4; i += stride) {
        float4 val = s4[i];
        uint2 o;
        o.x = packh2(val.x, val.y);
        o.y = packh2(val.z, val.w);
        *(uint2*)&dst[i * 4] = o;
    }
}

// ---------------------------------------------------------------------------
// QKV projection, fp16 mma.sync m16n8k16, 3-stage cp.async ring (R8).
// ---------------------------------------------------------------------------
#define GSTAGE 8192

__global__ __launch_bounds__(256, 2)
void qkv_gemm_f16(const float* __restrict__ bq,
                  const float* __restrict__ bk,
                  const float* __restrict__ bv)
{
    extern __shared__ uint32_t gsm[];

    const int z = blockIdx.z;
    const __half* X = g_X[z];
    const __half* W = g_W[z];
    const float* bias = (z == 0) ? bq : (z == 1) ? bk : bv;
    const float oscale = (z == 0) ? QSCALE : 1.f;

    const int m0 = blockIdx.x * 128;
    const int n0 = blockIdx.y * 128;
    const int tid  = threadIdx.x;
    const int warp = tid >> 5;
    const int lane = tid & 31;
    const int wm = warp >> 2;
    const int wn = warp & 3;
    const int lr = lane >> 2;
    const int lc = lane & 3;
    const int xr = lr << 2;

    float acc[4][4][4];
#pragma unroll
    for (int mi = 0; mi < 4; mi++)
#pragma unroll
        for (int ni = 0; ni < 4; ni++)
#pragma unroll
            for (int c = 0; c < 4; c++) acc[mi][ni][c] = 0.f;

    auto fill = [&](int it) {
        const int s = it % 3;
        const int kc = it * 64;
        uint32_t* Xs = gsm + s * GSTAGE;
        uint32_t* Ws = Xs + 4096;
#pragma unroll
        for (int e = tid; e < 1024; e += 256) {
            int r  = e >> 3;
            int c4 = e & 7;
            int pos = r * 32 + ((c4 * 4) ^ ((r & 7) << 2));
            cp16(saddr(&Xs[pos]), &X[(size_t)(m0 + r) * DD + kc + c4 * 8]);
            cp16(saddr(&Ws[pos]), &W[(size_t)(n0 + r) * DD + kc + c4 * 8]);
        }
    };

    fill(0); CP_COMMIT();
    fill(1); CP_COMMIT();

    for (int it = 0; it < 16; it++) {
        CP_WAIT1();
        __syncthreads();

        const uint32_t* Xc = gsm + (it % 3) * GSTAGE;
        const uint32_t* Wc = Xc + 4096;
#pragma unroll
        for (int ks = 0; ks < 4; ks++) {
            const int i0 = (8 * ks + lc) ^ xr;
            const int i1 = i0 ^ 4;
            uint32_t a[4][4];
#pragma unroll
            for (int mi = 0; mi < 4; mi++) {
                int row = wm * 64 + mi * 16 + lr;
                a[mi][0] = Xc[row * 32 + i0];
                a[mi][1] = Xc[(row + 8) * 32 + i0];
                a[mi][2] = Xc[row * 32 + i1];
                a[mi][3] = Xc[(row + 8) * 32 + i1];
            }
            uint32_t b[4][2];
#pragma unroll
            for (int ni = 0; ni < 4; ni++) {
                int col = wn * 32 + ni * 8 + lr;
                b[ni][0] = Wc[col * 32 + i0];
                b[ni][1] = Wc[col * 32 + i1];
            }
#pragma unroll
            for (int mi = 0; mi < 4; mi++)
#pragma unroll
                for (int ni = 0; ni < 4; ni++)
                    MMA_F16(acc[mi][ni], a[mi], b[ni]);
        }
        __syncthreads();
        if (it + 2 < 16) fill(it + 2);
        CP_COMMIT();
    }

    // epilogue: bias, scale, fp16-round; Q/K head-major, V transposed
#pragma unroll
    for (int mi = 0; mi < 4; mi++) {
#pragma unroll
        for (int ni = 0; ni < 4; ni++) {
            int m = m0 + wm * 64 + mi * 16 + lr;
            int n = n0 + wn * 32 + ni * 8 + 2 * lc;
            float b0 = __ldg(&bias[n]), b1 = __ldg(&bias[n + 1]);
            int h = n >> 6, d = n & 63;
#pragma unroll
            for (int half_ = 0; half_ < 2; half_++) {
                int mm = m + half_ * 8;
                int b_ = mm >> 11, s_ = mm & 2047;
                int bh = b_ * HH + h;
                float v0 = (acc[mi][ni][half_ * 2 + 0] + b0) * oscale;
                float v1 = (acc[mi][ni][half_ * 2 + 1] + b1) * oscale;
                if (z == 2) {
                    __half* vt = g_V + ((size_t)bh * DKK + d) * SS + s_;
                    vt[0]  = __float2half_rn(v0);
                    vt[SS] = __float2half_rn(v1);
                } else {
                    __half* dst = (z == 0) ? g_Q : g_K;
                    __half2 pk = __floats2half2_rn(v0, v1);
                    *(__half2*)&dst[((size_t)bh * SS + s_) * DKK + d] = pk;
                }
            }
        }
    }
}

// ---------------------------------------------------------------------------
// Causal flash attention, fp16 m16n8k16. BM=128, 8 warps x 16-row tiles.
// Q fragments hoisted to registers; P kept register-resident (C-frag of QK
// == A-frag of PV when nb-pairs pack the k=16 halves). smem: Q 16K + K 8K +
// V 8K = 32 KB. Split-issue cp.async pipeline. LPT tile order (heavy first).
// ---------------------------------------------------------------------------
__global__ __launch_bounds__(256, 2)
void flash_attn_f16(float* __restrict__ out)
{
    extern __shared__ uint32_t smu[];
    uint32_t* Qs = smu;                 // 128*32 words
    uint32_t* Ks = Qs + 128 * 32;       // 64*32
    uint32_t* Vs = Ks + 64 * 32;        // 64*32 (Vt tile: row=d, col=seq)

    const int bh = blockIdx.y;
    const int qt = gridDim.x - 1 - blockIdx.x;   // LPT: heavy tiles first
    const int m0 = qt * 128;

    const __half* Qp = g_Q + (size_t)bh * SS * DKK;
    const __half* Kp = g_K + (size_t)bh * SS * DKK;
    const __half* Vp = g_V + (size_t)bh * DKK * SS;   // transposed

    const int tid  = threadIdx.x;
    const int warp = tid >> 5;
    const int lane = tid & 31;
    const int lr = lane >> 2;
    const int lc = lane & 3;
    const int xr = lr << 2;
    const int wrow = warp * 16;

    auto issueK = [&](int t) {
        const int n0 = t * 64;
#pragma unroll
        for (int e = tid; e < 512; e += 256) {
            int r = e >> 3, c4 = e & 7;
            int pos = r * 32 + ((c4 * 4) ^ ((r & 7) << 2));
            cp16(saddr(&Ks[pos]), &Kp[(size_t)(n0 + r) * DKK + c4 * 8]);
        }
    };
    auto issueV = [&](int t) {
        const int n0 = t * 64;
#pragma unroll
        for (int e = tid; e < 512; e += 256) {
            int r = e >> 3, c4 = e & 7;
            int pos = r * 32 + ((c4 * 4) ^ ((r & 7) << 2));
            cp16(saddr(&Vs[pos]), &Vp[(size_t)r * SS + n0 + c4 * 8]);
        }
    };

    // prologue: Q group, K(0), V(0)
#pragma unroll
    for (int e = tid; e < 1024; e += 256) {
        int r = e >> 3, c4 = e & 7;
        int pos = r * 32 + ((c4 * 4) ^ ((r & 7) << 2));
        cp16(saddr(&Qs[pos]), &Qp[(size_t)(m0 + r) * DKK + c4 * 8]);
    }
    CP_COMMIT();
    issueK(0); CP_COMMIT();
    issueV(0); CP_COMMIT();

    // retire Q group; hoist Q fragments to registers
    CP_WAIT2();
    __syncthreads();
    uint32_t qa[4][4];
#pragma unroll
    for (int ks = 0; ks < 4; ks++) {
        const int i0 = (8 * ks + lc) ^ xr;
        const int i1 = i0 ^ 4;
        qa[ks][0] = Qs[(wrow + lr) * 32 + i0];
        qa[ks][1] = Qs[(wrow + lr + 8) * 32 + i0];
        qa[ks][2] = Qs[(wrow + lr) * 32 + i1];
        qa[ks][3] = Qs[(wrow + lr + 8) * 32 + i1];
    }

    float m_i[2], l_i[2], o[8][4];
    m_i[0] = m_i[1] = -1e30f;
    l_i[0] = l_i[1] = 0.f;
#pragma unroll
    for (int nb = 0; nb < 8; nb++)
#pragma unroll
        for (int c = 0; c < 4; c++) o[nb][c] = 0.f;

    const int ntiles = 2 * qt + 2;
    for (int t = 0; t < ntiles; t++) {
        const int n0 = t * 64;

        CP_WAIT1();            // K(t) ready (V(t) may pend)
        __syncthreads();

        // S = Q K^T (warp: 16x64), Q from registers
        float sc[8][4];
#pragma unroll
        for (int nb = 0; nb < 8; nb++)
#pragma unroll
            for (int c = 0; c < 4; c++) sc[nb][c] = 0.f;

#pragma unroll
        for (int ks = 0; ks < 4; ks++) {
            const int i0 = (8 * ks + lc) ^ xr;
            const int i1 = i0 ^ 4;
#pragma unroll
            for (int nb = 0; nb < 8; nb++) {
                uint32_t b[2];
                b[0] = Ks[(nb * 8 + lr) * 32 + i0];
                b[1] = Ks[(nb * 8 + lr) * 32 + i1];
                MMA_F16(sc[nb], qa[ks], b);
            }
        }
        __syncthreads();
        if (t + 1 < ntiles) issueK(t + 1);
        CP_COMMIT();

        // causal mask (diagonal tiles only)
        if (t >= 2 * qt) {
            const int row0 = m0 + wrow + lr;
            const int row1 = row0 + 8;
#pragma unroll
            for (int nb = 0; nb < 8; nb++) {
                int col = n0 + nb * 8 + 2 * lc;
                if (col > row0)     sc[nb][0] = -1e30f;
                if (col + 1 > row0) sc[nb][1] = -1e30f;
                if (col > row1)     sc[nb][2] = -1e30f;
                if (col + 1 > row1) sc[nb][3] = -1e30f;
            }
        }

        // online softmax (log2 domain), P packed into A-fragments in regs
        float rmax0 = -1e30f, rmax1 = -1e30f;
#pragma unroll
        for (int nb = 0; nb < 8; nb++) {
            rmax0 = fmaxf(rmax0, fmaxf(sc[nb][0], sc[nb][1]));
            rmax1 = fmaxf(rmax1, fmaxf(sc[nb][2], sc[nb][3]));
        }
#pragma unroll
        for (int off = 1; off < 4; off <<= 1) {
            rmax0 = fmaxf(rmax0, __shfl_xor_sync(0xffffffffu, rmax0, off));
            rmax1 = fmaxf(rmax1, __shfl_xor_sync(0xffffffffu, rmax1, off));
        }
        float mnew0 = fmaxf(m_i[0], rmax0);
        float mnew1 = fmaxf(m_i[1], rmax1);
        float corr0 = ex2(m_i[0] - mnew0);
        float corr1 = ex2(m_i[1] - mnew1);
        m_i[0] = mnew0; m_i[1] = mnew1;

        float rsum0 = 0.f, rsum1 = 0.f;
        uint32_t plo[8], phi[8];       // row lr / row lr+8 half2 packs
#pragma unroll
        for (int nb = 0; nb < 8; nb++) {
            float p0 = ex2(sc[nb][0] - mnew0);
            float p1 = ex2(sc[nb][1] - mnew0);
            float p2 = ex2(sc[nb][2] - mnew1);
            float p3 = ex2(sc[nb][3] - mnew1);
            rsum0 += p0 + p1;
            rsum1 += p2 + p3;
            plo[nb] = packh2(p0, p1);
            phi[nb] = packh2(p2, p3);
        }
#pragma unroll
        for (int off = 1; off < 4; off <<= 1) {
            rsum0 += __shfl_xor_sync(0xffffffffu, rsum0, off);
            rsum1 += __shfl_xor_sync(0xffffffffu, rsum1, off);
        }
        l_i[0] = l_i[0] * corr0 + rsum0;
        l_i[1] = l_i[1] * corr1 + rsum1;
#pragma unroll
        for (int nb = 0; nb < 8; nb++) {
            o[nb][0] *= corr0; o[nb][1] *= corr0;
            o[nb][2] *= corr1; o[nb][3] *= corr1;
        }

        CP_WAIT1();             // V(t) ready (K(t+1) may pend)
        __syncthreads();

        // O += P V  (A = register P, B = Vt rows like K)
#pragma unroll
        for (int j = 0; j < 4; j++) {
            uint32_t a[4];
            a[0] = plo[2 * j];
            a[1] = phi[2 * j];
            a[2] = plo[2 * j + 1];
            a[3] = phi[2 * j + 1];
            const int i0 = (8 * j + lc) ^ xr;
            const int i1 = i0 ^ 4;
#pragma unroll
            for (int nb = 0; nb < 8; nb++) {
                uint32_t b[2];
                b[0] = Vs[(nb * 8 + lr) * 32 + i0];
                b[1] = Vs[(nb * 8 + lr) * 32 + i1];
                MMA_F16(o[nb], a, b);
            }
        }
        __syncthreads();
        if (t + 1 < ntiles) issueV(t + 1);
        CP_COMMIT();
    }

    // epilogue
    const int b = bh >> 4;
    const int h = bh & 15;
    const float inv0 = 1.0f / l_i[0];
    const float inv1 = 1.0f / l_i[1];
    const int row0 = m0 + wrow + lr;
#pragma unroll
    for (int nb = 0; nb < 8; nb++) {
        int d = h * DKK + nb * 8 + 2 * lc;
        float2 v0, v1;
        v0.x = o[nb][0] * inv0; v0.y = o[nb][1] * inv0;
        v1.x = o[nb][2] * inv1; v1.y = o[nb][3] * inv1;
        *(float2*)&out[((size_t)(b * SS + row0)) * DD + d] = v0;
        *(float2*)&out[((size_t)(b * SS + row0 + 8)) * DD + d] = v1;
    }
}

// ---------------------------------------------------------------------------
extern "C" void kernel_launch(void* const* d_in, const int* in_sizes, int n_in,
                              void* d_out, int out_size)
{
    const float* q  = (const float*)d_in[0];
    const float* v  = (const float*)d_in[1];
    const float* k  = (const float*)d_in[2];
    // d_in[3] = attn_mask (causal, known analytically) — unused
    const float* Wq = (const float*)d_in[4];
    const float* bq = (const float*)d_in[5];
    const float* Wk = (const float*)d_in[6];
    const float* bk = (const float*)d_in[7];
    const float* Wv = (const float*)d_in[8];
    const float* bv = (const float*)d_in[9];
    float* out = (float*)d_out;

    cvt_prepass<<<dim3(2048, 6), 256>>>(q, k, v, Wq, Wk, Wv);

    const int gemmSmem = 3 * GSTAGE * sizeof(uint32_t);   // 98304
    cudaFuncSetAttribute(qkv_gemm_f16, cudaFuncAttributeMaxDynamicSharedMemorySize, gemmSmem);
    dim3 gGemm(MTOT / 128, DD / 128, 3);
    qkv_gemm_f16<<<gGemm, 256, gemmSmem>>>(bq, bk, bv);

    const int attnSmem = (128 * 32 + 64 * 32 + 64 * 32) * sizeof(uint32_t);  // 32768
    cudaFuncSetAttribute(flash_attn_f16, cudaFuncAttributeMaxDynamicSharedMemorySize, attnSmem);
    dim3 gAttn(SS / 128, BB * HH);
    flash_attn_f16<<<gAttn, 256, attnSmem>>>(out);
}

// round 10
// speedup vs baseline: 9.3712x; 1.0489x over previous
#include <cuda_runtime.h>
#include <cuda_fp16.h>
#include <cstdint>

#define BB 4
#define SS 2048
#define DD 1024
#define HH 16
#define DKK 64
#define MTOT (BB*SS)          // 8192

// log2(e) / sqrt(64) folded into Q projection
#define QSCALE 0.18033688011112042f

// fp16 scratch. g_V is stored TRANSPOSED: [B*H][DK][S].
__device__ __half g_Q[(size_t)MTOT * DD];
__device__ __half g_K[(size_t)MTOT * DD];
__device__ __half g_V[(size_t)MTOT * DD];
__device__ __half g_X[3][(size_t)MTOT * DD];   // fp16 inputs q,k,v
__device__ __half g_W[3][(size_t)DD * DD];     // fp16 weights

__device__ __forceinline__ float ex2(float x) {
    float y;
    asm("ex2.approx.ftz.f32 %0, %1;" : "=f"(y) : "f"(x));
    return y;
}
__device__ __forceinline__ uint32_t saddr(const void* p) {
    return (uint32_t)__cvta_generic_to_shared(p);
}
__device__ __forceinline__ void cp16(uint32_t s, const void* g) {
    asm volatile("cp.async.cg.shared.global [%0], [%1], 16;" :: "r"(s), "l"(g));
}
#define CP_COMMIT() asm volatile("cp.async.commit_group;")
#define CP_WAIT1()  asm volatile("cp.async.wait_group 1;")
#define CP_WAIT2()  asm volatile("cp.async.wait_group 2;")

#define MMA_F16(d, a, b)                                                      \
    asm volatile("mma.sync.aligned.m16n8k16.row.col.f32.f16.f16.f32 "         \
                 "{%0,%1,%2,%3}, {%4,%5,%6,%7}, {%8,%9}, {%0,%1,%2,%3};"      \
                 : "+f"(d[0]), "+f"(d[1]), "+f"(d[2]), "+f"(d[3])             \
                 : "r"(a[0]), "r"(a[1]), "r"(a[2]), "r"(a[3]),                \
                   "r"(b[0]), "r"(b[1]));

#define LDSM_X4(r0, r1, r2, r3, a_)                                           \
    asm volatile("ldmatrix.sync.aligned.m8n8.x4.shared.b16 {%0,%1,%2,%3}, [%4];" \
                 : "=r"(r0), "=r"(r1), "=r"(r2), "=r"(r3) : "r"(a_));

__device__ __forceinline__ uint32_t packh2(float a, float b) {
    __half2 h = __floats2half2_rn(a, b);
    return *(uint32_t*)&h;
}

// ---------------------------------------------------------------------------
// Pre-round pass: fp32 -> fp16 (rn).
// ---------------------------------------------------------------------------
__global__ void cvt_prepass(const float* __restrict__ q,
                            const float* __restrict__ k,
                            const float* __restrict__ v,
                            const float* __restrict__ Wq,
                            const float* __restrict__ Wk,
                            const float* __restrict__ Wv)
{
    const float* src; __half* dst; size_t n;
    switch (blockIdx.y) {
        case 0: src = q;  dst = g_X[0]; n = (size_t)MTOT * DD; break;
        case 1: src = k;  dst = g_X[1]; n = (size_t)MTOT * DD; break;
        case 2: src = v;  dst = g_X[2]; n = (size_t)MTOT * DD; break;
        case 3: src = Wq; dst = g_W[0]; n = (size_t)DD * DD;   break;
        case 4: src = Wk; dst = g_W[1]; n = (size_t)DD * DD;   break;
        default: src = Wv; dst = g_W[2]; n = (size_t)DD * DD;  break;
    }
    const float4* s4 = (const float4*)src;
    size_t n4 = n >> 2;
    size_t stride = (size_t)gridDim.x * blockDim.x;
    for (size_t i = (size_t)blockIdx.x * blockDim.x + threadIdx.x; i < n4; i += stride) {
        float4 val = s4[i];
        uint2 o;
        o.x = packh2(val.x, val.y);
        o.y = packh2(val.z, val.w);
        *(uint2*)&dst[i * 4] = o;
    }
}

// ---------------------------------------------------------------------------
// QKV projection, fp16 mma m16n8k16 + ldmatrix.x4, 3-stage cp.async ring.
// smem word layout: pos(r, w) = r*32 + (w ^ (4*(r&7))) -- each 8x8 b16
// submatrix (8 rows x 4 words) is a conflict-free 16B-chunk set for LDSM.
// ---------------------------------------------------------------------------
#define GSTAGE 8192

__global__ __launch_bounds__(256, 2)
void qkv_gemm_f16(const float* __restrict__ bq,
                  const float* __restrict__ bk,
                  const float* __restrict__ bv)
{
    extern __shared__ uint32_t gsm[];

    const int z = blockIdx.z;
    const __half* X = g_X[z];
    const __half* W = g_W[z];
    const float* bias = (z == 0) ? bq : (z == 1) ? bk : bv;
    const float oscale = (z == 0) ? QSCALE : 1.f;

    const int m0 = blockIdx.x * 128;
    const int n0 = blockIdx.y * 128;
    const int tid  = threadIdx.x;
    const int warp = tid >> 5;
    const int lane = tid & 31;
    const int wm = warp >> 2;
    const int wn = warp & 3;
    const int lr = lane >> 2;
    const int lc = lane & 3;

    // ldmatrix lane constants
    const int l7  = lane & 7;
    const int xr7 = l7 << 2;                    // swizzle XOR (words)
    const int gA  = (lane >> 3) & 1;            // A: row+8 select
    const int hA  = (lane >> 4) & 1;            // A: word-half select
    const int gB  = (lane >> 4) & 1;            // B: n-block select within pair
    const int hB  = (lane >> 3) & 1;            // B: word-half select
    const int arow_off = (8 * gA + l7) * 32;    // word offset
    const int brow_off = (8 * gB + l7) * 32;

    float acc[4][4][4];
#pragma unroll
    for (int mi = 0; mi < 4; mi++)
#pragma unroll
        for (int ni = 0; ni < 4; ni++)
#pragma unroll
            for (int c = 0; c < 4; c++) acc[mi][ni][c] = 0.f;

    auto fill = [&](int it) {
        const int s = it % 3;
        const int kc = it * 64;
        uint32_t* Xs = gsm + s * GSTAGE;
        uint32_t* Ws = Xs + 4096;
#pragma unroll
        for (int e = tid; e < 1024; e += 256) {
            int r  = e >> 3;
            int c4 = e & 7;
            int pos = r * 32 + ((c4 * 4) ^ ((r & 7) << 2));
            cp16(saddr(&Xs[pos]), &X[(size_t)(m0 + r) * DD + kc + c4 * 8]);
            cp16(saddr(&Ws[pos]), &W[(size_t)(n0 + r) * DD + kc + c4 * 8]);
        }
    };

    fill(0); CP_COMMIT();
    fill(1); CP_COMMIT();

    for (int it = 0; it < 16; it++) {
        CP_WAIT1();
        __syncthreads();

        const uint32_t xbase = saddr(gsm + (it % 3) * GSTAGE);
        const uint32_t wbase = xbase + 4096 * 4;
#pragma unroll
        for (int ks = 0; ks < 4; ks++) {
            const int waA = (8 * ks + 4 * hA) ^ xr7;
            const int waB = (8 * ks + 4 * hB) ^ xr7;
            uint32_t a[4][4];
#pragma unroll
            for (int mi = 0; mi < 4; mi++) {
                uint32_t ad = xbase + ((wm * 64 + mi * 16) * 32 + arow_off + waA) * 4;
                LDSM_X4(a[mi][0], a[mi][1], a[mi][2], a[mi][3], ad);
            }
            uint32_t b[4][2];
#pragma unroll
            for (int jp = 0; jp < 2; jp++) {
                uint32_t bd = wbase + ((wn * 32 + jp * 16) * 32 + brow_off + waB) * 4;
                LDSM_X4(b[2 * jp][0], b[2 * jp][1], b[2 * jp + 1][0], b[2 * jp + 1][1], bd);
            }
#pragma unroll
            for (int mi = 0; mi < 4; mi++)
#pragma unroll
                for (int ni = 0; ni < 4; ni++)
                    MMA_F16(acc[mi][ni], a[mi], b[ni]);
        }
        __syncthreads();
        if (it + 2 < 16) fill(it + 2);
        CP_COMMIT();
    }

    // epilogue: bias, scale, fp16-round; Q/K head-major, V transposed
#pragma unroll
    for (int mi = 0; mi < 4; mi++) {
#pragma unroll
        for (int ni = 0; ni < 4; ni++) {
            int m = m0 + wm * 64 + mi * 16 + lr;
            int n = n0 + wn * 32 + ni * 8 + 2 * lc;
            float b0 = __ldg(&bias[n]), b1 = __ldg(&bias[n + 1]);
            int h = n >> 6, d = n & 63;
#pragma unroll
            for (int half_ = 0; half_ < 2; half_++) {
                int mm = m + half_ * 8;
                int b_ = mm >> 11, s_ = mm & 2047;
                int bh = b_ * HH + h;
                float v0 = (acc[mi][ni][half_ * 2 + 0] + b0) * oscale;
                float v1 = (acc[mi][ni][half_ * 2 + 1] + b1) * oscale;
                if (z == 2) {
                    __half* vt = g_V + ((size_t)bh * DKK + d) * SS + s_;
                    vt[0]  = __float2half_rn(v0);
                    vt[SS] = __float2half_rn(v1);
                } else {
                    __half* dst = (z == 0) ? g_Q : g_K;
                    __half2 pk = __floats2half2_rn(v0, v1);
                    *(__half2*)&dst[((size_t)bh * SS + s_) * DKK + d] = pk;
                }
            }
        }
    }
}

// ---------------------------------------------------------------------------
// Causal flash attention, fp16 m16n8k16 + ldmatrix.x4. BM=128, 8 warps.
// Register-resident P; Q fragments hoisted. Split-issue cp.async pipeline.
// ---------------------------------------------------------------------------
__global__ __launch_bounds__(256, 2)
void flash_attn_f16(float* __restrict__ out)
{
    extern __shared__ uint32_t smu[];
    uint32_t* Qs = smu;                 // 128*32 words
    uint32_t* Ks = Qs + 128 * 32;       // 64*32
    uint32_t* Vs = Ks + 64 * 32;        // 64*32 (Vt tile: row=d, col=seq)

    const int bh = blockIdx.y;
    const int qt = gridDim.x - 1 - blockIdx.x;   // LPT: heavy tiles first
    const int m0 = qt * 128;

    const __half* Qp = g_Q + (size_t)bh * SS * DKK;
    const __half* Kp = g_K + (size_t)bh * SS * DKK;
    const __half* Vp = g_V + (size_t)bh * DKK * SS;   // transposed

    const int tid  = threadIdx.x;
    const int warp = tid >> 5;
    const int lane = tid & 31;
    const int lr = lane >> 2;
    const int lc = lane & 3;
    const int wrow = warp * 16;

    const int l7  = lane & 7;
    const int xr7 = l7 << 2;
    const int gA  = (lane >> 3) & 1;
    const int hA  = (lane >> 4) & 1;
    const int gB  = (lane >> 4) & 1;
    const int hB  = (lane >> 3) & 1;
    const int arow_off = (8 * gA + l7) * 32;
    const int brow_off = (8 * gB + l7) * 32;

    auto issueK = [&](int t) {
        const int n0 = t * 64;
#pragma unroll
        for (int e = tid; e < 512; e += 256) {
            int r = e >> 3, c4 = e & 7;
            int pos = r * 32 + ((c4 * 4) ^ ((r & 7) << 2));
            cp16(saddr(&Ks[pos]), &Kp[(size_t)(n0 + r) * DKK + c4 * 8]);
        }
    };
    auto issueV = [&](int t) {
        const int n0 = t * 64;
#pragma unroll
        for (int e = tid; e < 512; e += 256) {
            int r = e >> 3, c4 = e & 7;
            int pos = r * 32 + ((c4 * 4) ^ ((r & 7) << 2));
            cp16(saddr(&Vs[pos]), &Vp[(size_t)r * SS + n0 + c4 * 8]);
        }
    };

    // prologue: Q group, K(0), V(0)
#pragma unroll
    for (int e = tid; e < 1024; e += 256) {
        int r = e >> 3, c4 = e & 7;
        int pos = r * 32 + ((c4 * 4) ^ ((r & 7) << 2));
        cp16(saddr(&Qs[pos]), &Qp[(size_t)(m0 + r) * DKK + c4 * 8]);
    }
    CP_COMMIT();
    issueK(0); CP_COMMIT();
    issueV(0); CP_COMMIT();

    // retire Q group; hoist Q fragments via ldmatrix
    CP_WAIT2();
    __syncthreads();
    const uint32_t qbase = saddr(Qs);
    const uint32_t kbase = saddr(Ks);
    const uint32_t vbase = saddr(Vs);
    uint32_t qa[4][4];
#pragma unroll
    for (int ks = 0; ks < 4; ks++) {
        const int waA = (8 * ks + 4 * hA) ^ xr7;
        uint32_t ad = qbase + (wrow * 32 + arow_off + waA) * 4;
        LDSM_X4(qa[ks][0], qa[ks][1], qa[ks][2], qa[ks][3], ad);
    }

    float m_i[2], l_i[2], o[8][4];
    m_i[0] = m_i[1] = -1e30f;
    l_i[0] = l_i[1] = 0.f;
#pragma unroll
    for (int nb = 0; nb < 8; nb++)
#pragma unroll
        for (int c = 0; c < 4; c++) o[nb][c] = 0.f;

    const int ntiles = 2 * qt + 2;
    for (int t = 0; t < ntiles; t++) {
        const int n0 = t * 64;

        CP_WAIT1();            // K(t) ready (V(t) may pend)
        __syncthreads();

        // S = Q K^T (warp: 16x64)
        float sc[8][4];
#pragma unroll
        for (int nb = 0; nb < 8; nb++)
#pragma unroll
            for (int c = 0; c < 4; c++) sc[nb][c] = 0.f;

#pragma unroll
        for (int ks = 0; ks < 4; ks++) {
            const int waB = (8 * ks + 4 * hB) ^ xr7;
            uint32_t b[8][2];
#pragma unroll
            for (int jp = 0; jp < 4; jp++) {
                uint32_t bd = kbase + ((jp * 16) * 32 + brow_off + waB) * 4;
                LDSM_X4(b[2 * jp][0], b[2 * jp][1], b[2 * jp + 1][0], b[2 * jp + 1][1], bd);
            }
#pragma unroll
            for (int nb = 0; nb < 8; nb++)
                MMA_F16(sc[nb], qa[ks], b[nb]);
        }
        __syncthreads();
        if (t + 1 < ntiles) issueK(t + 1);
        CP_COMMIT();

        // causal mask (diagonal tiles only)
        if (t >= 2 * qt) {
            const int row0 = m0 + wrow + lr;
            const int row1 = row0 + 8;
#pragma unroll
            for (int nb = 0; nb < 8; nb++) {
                int col = n0 + nb * 8 + 2 * lc;
                if (col > row0)     sc[nb][0] = -1e30f;
                if (col + 1 > row0) sc[nb][1] = -1e30f;
                if (col > row1)     sc[nb][2] = -1e30f;
                if (col + 1 > row1) sc[nb][3] = -1e30f;
            }
        }

        // online softmax (log2 domain), P packed into A-fragments in regs
        float rmax0 = -1e30f, rmax1 = -1e30f;
#pragma unroll
        for (int nb = 0; nb < 8; nb++) {
            rmax0 = fmaxf(rmax0, fmaxf(sc[nb][0], sc[nb][1]));
            rmax1 = fmaxf(rmax1, fmaxf(sc[nb][2], sc[nb][3]));
        }
#pragma unroll
        for (int off = 1; off < 4; off <<= 1) {
            rmax0 = fmaxf(rmax0, __shfl_xor_sync(0xffffffffu, rmax0, off));
            rmax1 = fmaxf(rmax1, __shfl_xor_sync(0xffffffffu, rmax1, off));
        }
        float mnew0 = fmaxf(m_i[0], rmax0);
        float mnew1 = fmaxf(m_i[1], rmax1);
        float corr0 = ex2(m_i[0] - mnew0);
        float corr1 = ex2(m_i[1] - mnew1);
        m_i[0] = mnew0; m_i[1] = mnew1;

        float rsum0 = 0.f, rsum1 = 0.f;
        uint32_t plo[8], phi[8];
#pragma unroll
        for (int nb = 0; nb < 8; nb++) {
            float p0 = ex2(sc[nb][0] - mnew0);
            float p1 = ex2(sc[nb][1] - mnew0);
            float p2 = ex2(sc[nb][2] - mnew1);
            float p3 = ex2(sc[nb][3] - mnew1);
            rsum0 += p0 + p1;
            rsum1 += p2 + p3;
            plo[nb] = packh2(p0, p1);
            phi[nb] = packh2(p2, p3);
        }
#pragma unroll
        for (int off = 1; off < 4; off <<= 1) {
            rsum0 += __shfl_xor_sync(0xffffffffu, rsum0, off);
            rsum1 += __shfl_xor_sync(0xffffffffu, rsum1, off);
        }
        l_i[0] = l_i[0] * corr0 + rsum0;
        l_i[1] = l_i[1] * corr1 + rsum1;
#pragma unroll
        for (int nb = 0; nb < 8; nb++) {
            o[nb][0] *= corr0; o[nb][1] *= corr0;
            o[nb][2] *= corr1; o[nb][3] *= corr1;
        }

        CP_WAIT1();             // V(t) ready (K(t+1) may pend)
        __syncthreads();

        // O += P V  (A = register P, B = Vt rows)
#pragma unroll
        for (int j = 0; j < 4; j++) {
            uint32_t a[4];
            a[0] = plo[2 * j];
            a[1] = phi[2 * j];
            a[2] = plo[2 * j + 1];
            a[3] = phi[2 * j + 1];
            const int waB = (8 * j + 4 * hB) ^ xr7;
            uint32_t b[8][2];
#pragma unroll
            for (int jp = 0; jp < 4; jp++) {
                uint32_t bd = vbase + ((jp * 16) * 32 + brow_off + waB) * 4;
                LDSM_X4(b[2 * jp][0], b[2 * jp][1], b[2 * jp + 1][0], b[2 * jp + 1][1], bd);
            }
#pragma unroll
            for (int nb = 0; nb < 8; nb++)
                MMA_F16(o[nb], a, b[nb]);
        }
        __syncthreads();
        if (t + 1 < ntiles) issueV(t + 1);
        CP_COMMIT();
    }

    // epilogue
    const int b = bh >> 4;
    const int h = bh & 15;
    const float inv0 = 1.0f / l_i[0];
    const float inv1 = 1.0f / l_i[1];
    const int row0 = m0 + wrow + lr;
#pragma unroll
    for (int nb = 0; nb < 8; nb++) {
        int d = h * DKK + nb * 8 + 2 * lc;
        float2 v0, v1;
        v0.x = o[nb][0] * inv0; v0.y = o[nb][1] * inv0;
        v1.x = o[nb][2] * inv1; v1.y = o[nb][3] * inv1;
        *(float2*)&out[((size_t)(b * SS + row0)) * DD + d] = v0;
        *(float2*)&out[((size_t)(b * SS + row0 + 8)) * DD + d] = v1;
    }
}

// ---------------------------------------------------------------------------
extern "C" void kernel_launch(void* const* d_in, const int* in_sizes, int n_in,
                              void* d_out, int out_size)
{
    const float* q  = (const float*)d_in[0];
    const float* v  = (const float*)d_in[1];
    const float* k  = (const float*)d_in[2];
    // d_in[3] = attn_mask (causal, known analytically) — unused
    const float* Wq = (const float*)d_in[4];
    const float* bq = (const float*)d_in[5];
    const float* Wk = (const float*)d_in[6];
    const float* bk = (const float*)d_in[7];
    const float* Wv = (const float*)d_in[8];
    const float* bv = (const float*)d_in[9];
    float* out = (float*)d_out;

    cvt_prepass<<<dim3(2048, 6), 256>>>(q, k, v, Wq, Wk, Wv);

    const int gemmSmem = 3 * GSTAGE * sizeof(uint32_t);   // 98304
    cudaFuncSetAttribute(qkv_gemm_f16, cudaFuncAttributeMaxDynamicSharedMemorySize, gemmSmem);
    dim3 gGemm(MTOT / 128, DD / 128, 3);
    qkv_gemm_f16<<<gGemm, 256, gemmSmem>>>(bq, bk, bv);

    const int attnSmem = (128 * 32 + 64 * 32 + 64 * 32) * sizeof(uint32_t);  // 32768
    cudaFuncSetAttribute(flash_attn_f16, cudaFuncAttributeMaxDynamicSharedMemorySize, attnSmem);
    dim3 gAttn(SS / 128, BB * HH);
    flash_attn_f16<<<gAttn, 256, attnSmem>>>(out);
}

// round 11
// speedup vs baseline: 9.5021x; 1.0140x over previous
#include <cuda_runtime.h>
#include <cuda_fp16.h>
#include <cstdint>

#define BB 4
#define SS 2048
#define DD 1024
#define HH 16
#define DKK 64
#define MTOT (BB*SS)          // 8192

// log2(e) / sqrt(64) folded into Q projection
#define QSCALE 0.18033688011112042f

// fp16 scratch. g_V is stored TRANSPOSED: [B*H][DK][S].
__device__ __half g_Q[(size_t)MTOT * DD];
__device__ __half g_K[(size_t)MTOT * DD];
__device__ __half g_V[(size_t)MTOT * DD];
__device__ __half g_X[3][(size_t)MTOT * DD];   // fp16 inputs q,k,v
__device__ __half g_W[3][(size_t)DD * DD];     // fp16 weights

__device__ __forceinline__ float ex2(float x) {
    float y;
    asm("ex2.approx.ftz.f32 %0, %1;" : "=f"(y) : "f"(x));
    return y;
}
__device__ __forceinline__ uint32_t saddr(const void* p) {
    return (uint32_t)__cvta_generic_to_shared(p);
}
__device__ __forceinline__ void cp16(uint32_t s, const void* g) {
    asm volatile("cp.async.cg.shared.global [%0], [%1], 16;" :: "r"(s), "l"(g));
}
#define CP_COMMIT() asm volatile("cp.async.commit_group;")
#define CP_WAIT1()  asm volatile("cp.async.wait_group 1;")
#define CP_WAIT2()  asm volatile("cp.async.wait_group 2;")

#define MMA_F16(d, a, b)                                                      \
    asm volatile("mma.sync.aligned.m16n8k16.row.col.f32.f16.f16.f32 "         \
                 "{%0,%1,%2,%3}, {%4,%5,%6,%7}, {%8,%9}, {%0,%1,%2,%3};"      \
                 : "+f"(d[0]), "+f"(d[1]), "+f"(d[2]), "+f"(d[3])             \
                 : "r"(a[0]), "r"(a[1]), "r"(a[2]), "r"(a[3]),                \
                   "r"(b[0]), "r"(b[1]));

#define LDSM_X4(r0, r1, r2, r3, a_)                                           \
    asm volatile("ldmatrix.sync.aligned.m8n8.x4.shared.b16 {%0,%1,%2,%3}, [%4];" \
                 : "=r"(r0), "=r"(r1), "=r"(r2), "=r"(r3) : "r"(a_));

__device__ __forceinline__ uint32_t packh2(float a, float b) {
    __half2 h = __floats2half2_rn(a, b);
    return *(uint32_t*)&h;
}

// ---------------------------------------------------------------------------
// Pre-round pass: fp32 -> fp16 (rn).
// ---------------------------------------------------------------------------
__global__ void cvt_prepass(const float* __restrict__ q,
                            const float* __restrict__ k,
                            const float* __restrict__ v,
                            const float* __restrict__ Wq,
                            const float* __restrict__ Wk,
                            const float* __restrict__ Wv)
{
    const float* src; __half* dst; size_t n;
    switch (blockIdx.y) {
        case 0: src = q;  dst = g_X[0]; n = (size_t)MTOT * DD; break;
        case 1: src = k;  dst = g_X[1]; n = (size_t)MTOT * DD; break;
        case 2: src = v;  dst = g_X[2]; n = (size_t)MTOT * DD; break;
        case 3: src = Wq; dst = g_W[0]; n = (size_t)DD * DD;   break;
        case 4: src = Wk; dst = g_W[1]; n = (size_t)DD * DD;   break;
        default: src = Wv; dst = g_W[2]; n = (size_t)DD * DD;  break;
    }
    const float4* s4 = (const float4*)src;
    size_t n4 = n >> 2;
    size_t stride = (size_t)gridDim.x * blockDim.x;
    for (size_t i = (size_t)blockIdx.x * blockDim.x + threadIdx.x; i < n4; i += stride) {
        float4 val = s4[i];
        uint2 o;
        o.x = packh2(val.x, val.y);
        o.y = packh2(val.z, val.w);
        *(uint2*)&dst[i * 4] = o;
    }
}

// ---------------------------------------------------------------------------
// QKV projection, fp16 mma m16n8k16 + ldmatrix.x4, 3-stage cp.async ring.
// One barrier per K-chunk: wait -> bar -> fill(it+2) -> MMA(it).
// ---------------------------------------------------------------------------
#define GSTAGE 8192

__global__ __launch_bounds__(256, 2)
void qkv_gemm_f16(const float* __restrict__ bq,
                  const float* __restrict__ bk,
                  const float* __restrict__ bv)
{
    extern __shared__ uint32_t gsm[];

    const int z = blockIdx.z;
    const __half* X = g_X[z];
    const __half* W = g_W[z];
    const float* bias = (z == 0) ? bq : (z == 1) ? bk : bv;
    const float oscale = (z == 0) ? QSCALE : 1.f;

    const int m0 = blockIdx.x * 128;
    const int n0 = blockIdx.y * 128;
    const int tid  = threadIdx.x;
    const int warp = tid >> 5;
    const int lane = tid & 31;
    const int wm = warp >> 2;
    const int wn = warp & 3;
    const int lr = lane >> 2;
    const int lc = lane & 3;

    const int l7  = lane & 7;
    const int xr7 = l7 << 2;
    const int gA  = (lane >> 3) & 1;
    const int hA  = (lane >> 4) & 1;
    const int gB  = (lane >> 4) & 1;
    const int hB  = (lane >> 3) & 1;
    const int arow_off = (8 * gA + l7) * 32;
    const int brow_off = (8 * gB + l7) * 32;

    float acc[4][4][4];
#pragma unroll
    for (int mi = 0; mi < 4; mi++)
#pragma unroll
        for (int ni = 0; ni < 4; ni++)
#pragma unroll
            for (int c = 0; c < 4; c++) acc[mi][ni][c] = 0.f;

    auto fill = [&](int it) {
        const int s = it % 3;
        const int kc = it * 64;
        uint32_t* Xs = gsm + s * GSTAGE;
        uint32_t* Ws = Xs + 4096;
#pragma unroll
        for (int e = tid; e < 1024; e += 256) {
            int r  = e >> 3;
            int c4 = e & 7;
            int pos = r * 32 + ((c4 * 4) ^ ((r & 7) << 2));
            cp16(saddr(&Xs[pos]), &X[(size_t)(m0 + r) * DD + kc + c4 * 8]);
            cp16(saddr(&Ws[pos]), &W[(size_t)(n0 + r) * DD + kc + c4 * 8]);
        }
    };

    fill(0); CP_COMMIT();
    fill(1); CP_COMMIT();

    for (int it = 0; it < 16; it++) {
        CP_WAIT1();             // chunk(it) resident; chunk(it+1) may pend
        __syncthreads();        // all warps done reading stage (it-1)%3

        if (it + 2 < 16) fill(it + 2);   // stage (it+2)%3 == (it-1)%3: safe
        CP_COMMIT();

        const uint32_t xbase = saddr(gsm + (it % 3) * GSTAGE);
        const uint32_t wbase = xbase + 4096 * 4;
#pragma unroll
        for (int ks = 0; ks < 4; ks++) {
            const int waA = (8 * ks + 4 * hA) ^ xr7;
            const int waB = (8 * ks + 4 * hB) ^ xr7;
            uint32_t a[4][4];
#pragma unroll
            for (int mi = 0; mi < 4; mi++) {
                uint32_t ad = xbase + ((wm * 64 + mi * 16) * 32 + arow_off + waA) * 4;
                LDSM_X4(a[mi][0], a[mi][1], a[mi][2], a[mi][3], ad);
            }
            uint32_t b[4][2];
#pragma unroll
            for (int jp = 0; jp < 2; jp++) {
                uint32_t bd = wbase + ((wn * 32 + jp * 16) * 32 + brow_off + waB) * 4;
                LDSM_X4(b[2 * jp][0], b[2 * jp][1], b[2 * jp + 1][0], b[2 * jp + 1][1], bd);
            }
#pragma unroll
            for (int mi = 0; mi < 4; mi++)
#pragma unroll
                for (int ni = 0; ni < 4; ni++)
                    MMA_F16(acc[mi][ni], a[mi], b[ni]);
        }
    }

    // epilogue: bias, scale, fp16-round; Q/K head-major, V transposed
#pragma unroll
    for (int mi = 0; mi < 4; mi++) {
#pragma unroll
        for (int ni = 0; ni < 4; ni++) {
            int m = m0 + wm * 64 + mi * 16 + lr;
            int n = n0 + wn * 32 + ni * 8 + 2 * lc;
            float b0 = __ldg(&bias[n]), b1 = __ldg(&bias[n + 1]);
            int h = n >> 6, d = n & 63;
#pragma unroll
            for (int half_ = 0; half_ < 2; half_++) {
                int mm = m + half_ * 8;
                int b_ = mm >> 11, s_ = mm & 2047;
                int bh = b_ * HH + h;
                float v0 = (acc[mi][ni][half_ * 2 + 0] + b0) * oscale;
                float v1 = (acc[mi][ni][half_ * 2 + 1] + b1) * oscale;
                if (z == 2) {
                    __half* vt = g_V + ((size_t)bh * DKK + d) * SS + s_;
                    vt[0]  = __float2half_rn(v0);
                    vt[SS] = __float2half_rn(v1);
                } else {
                    __half* dst = (z == 0) ? g_Q : g_K;
                    __half2 pk = __floats2half2_rn(v0, v1);
                    *(__half2*)&dst[((size_t)bh * SS + s_) * DKK + d] = pk;
                }
            }
        }
    }
}

// ---------------------------------------------------------------------------
// Causal flash attention, fp16 m16n8k16 + ldmatrix.x4. BM=128, 8 warps.
// Register-resident P; Q fragments hoisted. 3-stage combined K+V ring:
// ONE barrier + ONE wait per KV tile; two tiles always in flight.
// smem: Q 16KB + 3 x (K 8KB + V 8KB) = 64KB -> 2 CTAs/SM.
// ---------------------------------------------------------------------------
#define AKV 4096   // words per KV stage (K 2048 + V 2048)

__global__ __launch_bounds__(256, 2)
void flash_attn_f16(float* __restrict__ out)
{
    extern __shared__ uint32_t smu[];
    uint32_t* Qs  = smu;                 // 128*32 words
    uint32_t* KV0 = smu + 128 * 32;      // 3 stages x [K 64*32 | V 64*32]

    const int bh = blockIdx.y;
    const int qt = gridDim.x - 1 - blockIdx.x;   // LPT: heavy tiles first
    const int m0 = qt * 128;

    const __half* Qp = g_Q + (size_t)bh * SS * DKK;
    const __half* Kp = g_K + (size_t)bh * SS * DKK;
    const __half* Vp = g_V + (size_t)bh * DKK * SS;   // transposed

    const int tid  = threadIdx.x;
    const int warp = tid >> 5;
    const int lane = tid & 31;
    const int lr = lane >> 2;
    const int lc = lane & 3;
    const int wrow = warp * 16;

    const int l7  = lane & 7;
    const int xr7 = l7 << 2;
    const int hA  = (lane >> 4) & 1;
    const int gA  = (lane >> 3) & 1;
    const int gB  = (lane >> 4) & 1;
    const int hB  = (lane >> 3) & 1;
    const int arow_off = (8 * gA + l7) * 32;
    const int brow_off = (8 * gB + l7) * 32;

    // one combined K+V tile fill (single commit group)
    auto fillKV = [&](int t) {
        const int n0 = t * 64;
        uint32_t* Ks = KV0 + (t % 3) * AKV;
        uint32_t* Vs = Ks + 2048;
#pragma unroll
        for (int e = tid; e < 512; e += 256) {
            int r = e >> 3, c4 = e & 7;
            int pos = r * 32 + ((c4 * 4) ^ ((r & 7) << 2));
            cp16(saddr(&Ks[pos]), &Kp[(size_t)(n0 + r) * DKK + c4 * 8]);
            cp16(saddr(&Vs[pos]), &Vp[(size_t)r * SS + n0 + c4 * 8]);
        }
    };

    // prologue: Q group, KV(0), KV(1)
#pragma unroll
    for (int e = tid; e < 1024; e += 256) {
        int r = e >> 3, c4 = e & 7;
        int pos = r * 32 + ((c4 * 4) ^ ((r & 7) << 2));
        cp16(saddr(&Qs[pos]), &Qp[(size_t)(m0 + r) * DKK + c4 * 8]);
    }
    CP_COMMIT();
    fillKV(0); CP_COMMIT();
    const int ntiles = 2 * qt + 2;
    if (1 < ntiles) fillKV(1);
    CP_COMMIT();

    // retire Q group; hoist Q fragments via ldmatrix
    CP_WAIT2();
    __syncthreads();
    uint32_t qa[4][4];
#pragma unroll
    for (int ks = 0; ks < 4; ks++) {
        const int waA = (8 * ks + 4 * hA) ^ xr7;
        uint32_t ad = saddr(Qs) + (wrow * 32 + arow_off + waA) * 4;
        LDSM_X4(qa[ks][0], qa[ks][1], qa[ks][2], qa[ks][3], ad);
    }

    float m_i[2], l_i[2], o[8][4];
    m_i[0] = m_i[1] = -1e30f;
    l_i[0] = l_i[1] = 0.f;
#pragma unroll
    for (int nb = 0; nb < 8; nb++)
#pragma unroll
        for (int c = 0; c < 4; c++) o[nb][c] = 0.f;

    for (int t = 0; t < ntiles; t++) {
        const int n0 = t * 64;

        CP_WAIT1();            // KV(t) resident; KV(t+1) may pend
        __syncthreads();       // all warps done reading stage (t-1)%3

        if (t + 2 < ntiles) fillKV(t + 2);   // stage (t+2)%3 == (t-1)%3: safe
        CP_COMMIT();

        const uint32_t kbase = saddr(KV0 + (t % 3) * AKV);
        const uint32_t vbase = kbase + 2048 * 4;

        // S = Q K^T (warp: 16x64)
        float sc[8][4];
#pragma unroll
        for (int nb = 0; nb < 8; nb++)
#pragma unroll
            for (int c = 0; c < 4; c++) sc[nb][c] = 0.f;

#pragma unroll
        for (int ks = 0; ks < 4; ks++) {
            const int waB = (8 * ks + 4 * hB) ^ xr7;
            uint32_t b[8][2];
#pragma unroll
            for (int jp = 0; jp < 4; jp++) {
                uint32_t bd = kbase + ((jp * 16) * 32 + brow_off + waB) * 4;
                LDSM_X4(b[2 * jp][0], b[2 * jp][1], b[2 * jp + 1][0], b[2 * jp + 1][1], bd);
            }
#pragma unroll
            for (int nb = 0; nb < 8; nb++)
                MMA_F16(sc[nb], qa[ks], b[nb]);
        }

        // causal mask (diagonal tiles only)
        if (t >= 2 * qt) {
            const int row0 = m0 + wrow + lr;
            const int row1 = row0 + 8;
#pragma unroll
            for (int nb = 0; nb < 8; nb++) {
                int col = n0 + nb * 8 + 2 * lc;
                if (col > row0)     sc[nb][0] = -1e30f;
                if (col + 1 > row0) sc[nb][1] = -1e30f;
                if (col > row1)     sc[nb][2] = -1e30f;
                if (col + 1 > row1) sc[nb][3] = -1e30f;
            }
        }

        // online softmax (log2 domain), P packed into A-fragments in regs
        float rmax0 = -1e30f, rmax1 = -1e30f;
#pragma unroll
        for (int nb = 0; nb < 8; nb++) {
            rmax0 = fmaxf(rmax0, fmaxf(sc[nb][0], sc[nb][1]));
            rmax1 = fmaxf(rmax1, fmaxf(sc[nb][2], sc[nb][3]));
        }
#pragma unroll
        for (int off = 1; off < 4; off <<= 1) {
            rmax0 = fmaxf(rmax0, __shfl_xor_sync(0xffffffffu, rmax0, off));
            rmax1 = fmaxf(rmax1, __shfl_xor_sync(0xffffffffu, rmax1, off));
        }
        float mnew0 = fmaxf(m_i[0], rmax0);
        float mnew1 = fmaxf(m_i[1], rmax1);
        float corr0 = ex2(m_i[0] - mnew0);
        float corr1 = ex2(m_i[1] - mnew1);
        m_i[0] = mnew0; m_i[1] = mnew1;

        float rsum0 = 0.f, rsum1 = 0.f;
        uint32_t plo[8], phi[8];
#pragma unroll
        for (int nb = 0; nb < 8; nb++) {
            float p0 = ex2(sc[nb][0] - mnew0);
            float p1 = ex2(sc[nb][1] - mnew0);
            float p2 = ex2(sc[nb][2] - mnew1);
            float p3 = ex2(sc[nb][3] - mnew1);
            rsum0 += p0 + p1;
            rsum1 += p2 + p3;
            plo[nb] = packh2(p0, p1);
            phi[nb] = packh2(p2, p3);
        }
#pragma unroll
        for (int off = 1; off < 4; off <<= 1) {
            rsum0 += __shfl_xor_sync(0xffffffffu, rsum0, off);
            rsum1 += __shfl_xor_sync(0xffffffffu, rsum1, off);
        }
        l_i[0] = l_i[0] * corr0 + rsum0;
        l_i[1] = l_i[1] * corr1 + rsum1;
#pragma unroll
        for (int nb = 0; nb < 8; nb++) {
            o[nb][0] *= corr0; o[nb][1] *= corr0;
            o[nb][2] *= corr1; o[nb][3] *= corr1;
        }

        // O += P V  (A = register P, B = Vt rows)
#pragma unroll
        for (int j = 0; j < 4; j++) {
            uint32_t a[4];
            a[0] = plo[2 * j];
            a[1] = phi[2 * j];
            a[2] = plo[2 * j + 1];
            a[3] = phi[2 * j + 1];
            const int waB = (8 * j + 4 * hB) ^ xr7;
            uint32_t b[8][2];
#pragma unroll
            for (int jp = 0; jp < 4; jp++) {
                uint32_t bd = vbase + ((jp * 16) * 32 + brow_off + waB) * 4;
                LDSM_X4(b[2 * jp][0], b[2 * jp][1], b[2 * jp + 1][0], b[2 * jp + 1][1], bd);
            }
#pragma unroll
            for (int nb = 0; nb < 8; nb++)
                MMA_F16(o[nb], a, b[nb]);
        }
    }

    // epilogue
    const int b = bh >> 4;
    const int h = bh & 15;
    const float inv0 = 1.0f / l_i[0];
    const float inv1 = 1.0f / l_i[1];
    const int row0 = m0 + wrow + lr;
#pragma unroll
    for (int nb = 0; nb < 8; nb++) {
        int d = h * DKK + nb * 8 + 2 * lc;
        float2 v0, v1;
        v0.x = o[nb][0] * inv0; v0.y = o[nb][1] * inv0;
        v1.x = o[nb][2] * inv1; v1.y = o[nb][3] * inv1;
        *(float2*)&out[((size_t)(b * SS + row0)) * DD + d] = v0;
        *(float2*)&out[((size_t)(b * SS + row0 + 8)) * DD + d] = v1;
    }
}

// ---------------------------------------------------------------------------
extern "C" void kernel_launch(void* const* d_in, const int* in_sizes, int n_in,
                              void* d_out, int out_size)
{
    const float* q  = (const float*)d_in[0];
    const float* v  = (const float*)d_in[1];
    const float* k  = (const float*)d_in[2];
    // d_in[3] = attn_mask (causal, known analytically) — unused
    const float* Wq = (const float*)d_in[4];
    const float* bq = (const float*)d_in[5];
    const float* Wk = (const float*)d_in[6];
    const float* bk = (const float*)d_in[7];
    const float* Wv = (const float*)d_in[8];
    const float* bv = (const float*)d_in[9];
    float* out = (float*)d_out;

    cvt_prepass<<<dim3(2048, 6), 256>>>(q, k, v, Wq, Wk, Wv);

    const int gemmSmem = 3 * GSTAGE * sizeof(uint32_t);   // 98304
    cudaFuncSetAttribute(qkv_gemm_f16, cudaFuncAttributeMaxDynamicSharedMemorySize, gemmSmem);
    dim3 gGemm(MTOT / 128, DD / 128, 3);
    qkv_gemm_f16<<<gGemm, 256, gemmSmem>>>(bq, bk, bv);

    const int attnSmem = (128 * 32 + 3 * AKV) * sizeof(uint32_t);  // 65536
    cudaFuncSetAttribute(flash_attn_f16, cudaFuncAttributeMaxDynamicSharedMemorySize, attnSmem);
    dim3 gAttn(SS / 128, BB * HH);
    flash_attn_f16<<<gAttn, 256, attnSmem>>>(out);
}

// round 12
// speedup vs baseline: 9.5779x; 1.0080x over previous
#include <cuda_runtime.h>
#include <cuda_fp16.h>
#include <cstdint>

#define BB 4
#define SS 2048
#define DD 1024
#define HH 16
#define DKK 64
#define MTOT (BB*SS)          // 8192

// log2(e) / sqrt(64) folded into Q projection
#define QSCALE 0.18033688011112042f

// fp16 scratch. g_V is stored TRANSPOSED: [B*H][DK][S].
__device__ __half g_Q[(size_t)MTOT * DD];
__device__ __half g_K[(size_t)MTOT * DD];
__device__ __half g_V[(size_t)MTOT * DD];
__device__ __half g_X[3][(size_t)MTOT * DD];   // fp16 inputs q,k,v
__device__ __half g_W[3][(size_t)DD * DD];     // fp16 weights

__device__ __forceinline__ float ex2(float x) {
    float y;
    asm("ex2.approx.ftz.f32 %0, %1;" : "=f"(y) : "f"(x));
    return y;
}
__device__ __forceinline__ uint32_t h2ex2(uint32_t x) {
    uint32_t y;
    asm("ex2.approx.f16x2 %0, %1;" : "=r"(y) : "r"(x));
    return y;
}
__device__ __forceinline__ uint32_t saddr(const void* p) {
    return (uint32_t)__cvta_generic_to_shared(p);
}
__device__ __forceinline__ void cp16(uint32_t s, const void* g) {
    asm volatile("cp.async.cg.shared.global [%0], [%1], 16;" :: "r"(s), "l"(g));
}
#define CP_COMMIT() asm volatile("cp.async.commit_group;")
#define CP_WAIT1()  asm volatile("cp.async.wait_group 1;")
#define CP_WAIT2()  asm volatile("cp.async.wait_group 2;")

#define MMA_F16(d, a, b)                                                      \
    asm volatile("mma.sync.aligned.m16n8k16.row.col.f32.f16.f16.f32 "         \
                 "{%0,%1,%2,%3}, {%4,%5,%6,%7}, {%8,%9}, {%0,%1,%2,%3};"      \
                 : "+f"(d[0]), "+f"(d[1]), "+f"(d[2]), "+f"(d[3])             \
                 : "r"(a[0]), "r"(a[1]), "r"(a[2]), "r"(a[3]),                \
                   "r"(b[0]), "r"(b[1]));

#define LDSM_X4(r0, r1, r2, r3, a_)                                           \
    asm volatile("ldmatrix.sync.aligned.m8n8.x4.shared.b16 {%0,%1,%2,%3}, [%4];" \
                 : "=r"(r0), "=r"(r1), "=r"(r2), "=r"(r3) : "r"(a_));

__device__ __forceinline__ uint32_t packh2(float a, float b) {
    __half2 h = __floats2half2_rn(a, b);
    return *(uint32_t*)&h;
}

// ---------------------------------------------------------------------------
// Pre-round pass: fp32 -> fp16 (rn).
// ---------------------------------------------------------------------------
__global__ void cvt_prepass(const float* __restrict__ q,
                            const float* __restrict__ k,
                            const float* __restrict__ v,
                            const float* __restrict__ Wq,
                            const float* __restrict__ Wk,
                            const float* __restrict__ Wv)
{
    const float* src; __half* dst; size_t n;
    switch (blockIdx.y) {
        case 0: src = q;  dst = g_X[0]; n = (size_t)MTOT * DD; break;
        case 1: src = k;  dst = g_X[1]; n = (size_t)MTOT * DD; break;
        case 2: src = v;  dst = g_X[2]; n = (size_t)MTOT * DD; break;
        case 3: src = Wq; dst = g_W[0]; n = (size_t)DD * DD;   break;
        case 4: src = Wk; dst = g_W[1]; n = (size_t)DD * DD;   break;
        default: src = Wv; dst = g_W[2]; n = (size_t)DD * DD;  break;
    }
    const float4* s4 = (const float4*)src;
    size_t n4 = n >> 2;
    size_t stride = (size_t)gridDim.x * blockDim.x;
    for (size_t i = (size_t)blockIdx.x * blockDim.x + threadIdx.x; i < n4; i += stride) {
        float4 val = s4[i];
        uint2 o;
        o.x = packh2(val.x, val.y);
        o.y = packh2(val.z, val.w);
        *(uint2*)&dst[i * 4] = o;
    }
}

// ---------------------------------------------------------------------------
// QKV projection, fp16 mma m16n8k16 + ldmatrix.x4, 3-stage cp.async ring.
// PERSISTENT: grid 296 CTAs loop over the 1536 logical 128x128 tiles.
// ---------------------------------------------------------------------------
#define GSTAGE 8192
#define GEMM_TILES 1536   // 64 m-blocks x 8 n-blocks x 3 matrices

__global__ __launch_bounds__(256, 2)
void qkv_gemm_f16(const float* __restrict__ bq,
                  const float* __restrict__ bk,
                  const float* __restrict__ bv)
{
    extern __shared__ uint32_t gsm[];

    const int tid  = threadIdx.x;
    const int warp = tid >> 5;
    const int lane = tid & 31;
    const int wm = warp >> 2;
    const int wn = warp & 3;
    const int lr = lane >> 2;
    const int lc = lane & 3;

    const int l7  = lane & 7;
    const int xr7 = l7 << 2;
    const int gA  = (lane >> 3) & 1;
    const int hA  = (lane >> 4) & 1;
    const int gB  = (lane >> 4) & 1;
    const int hB  = (lane >> 3) & 1;
    const int arow_off = (8 * gA + l7) * 32;
    const int brow_off = (8 * gB + l7) * 32;

    for (int tile = blockIdx.x; tile < GEMM_TILES; tile += gridDim.x) {
        const int z   = tile >> 9;          // /512
        const int rem = tile & 511;
        const int m0  = (rem >> 3) * 128;
        const int n0  = (rem & 7) * 128;

        const __half* X = g_X[z];
        const __half* W = g_W[z];
        const float* bias = (z == 0) ? bq : (z == 1) ? bk : bv;
        const float oscale = (z == 0) ? QSCALE : 1.f;

        float acc[4][4][4];
#pragma unroll
        for (int mi = 0; mi < 4; mi++)
#pragma unroll
            for (int ni = 0; ni < 4; ni++)
#pragma unroll
                for (int c = 0; c < 4; c++) acc[mi][ni][c] = 0.f;

        auto fill = [&](int it) {
            const int s = it % 3;
            const int kc = it * 64;
            uint32_t* Xs = gsm + s * GSTAGE;
            uint32_t* Ws = Xs + 4096;
#pragma unroll
            for (int e = tid; e < 1024; e += 256) {
                int r  = e >> 3;
                int c4 = e & 7;
                int pos = r * 32 + ((c4 * 4) ^ ((r & 7) << 2));
                cp16(saddr(&Xs[pos]), &X[(size_t)(m0 + r) * DD + kc + c4 * 8]);
                cp16(saddr(&Ws[pos]), &W[(size_t)(n0 + r) * DD + kc + c4 * 8]);
            }
        };

        __syncthreads();        // all warps done with previous tile's smem
        fill(0); CP_COMMIT();
        fill(1); CP_COMMIT();

        for (int it = 0; it < 16; it++) {
            CP_WAIT1();
            __syncthreads();

            if (it + 2 < 16) fill(it + 2);
            CP_COMMIT();

            const uint32_t xbase = saddr(gsm + (it % 3) * GSTAGE);
            const uint32_t wbase = xbase + 4096 * 4;
#pragma unroll
            for (int ks = 0; ks < 4; ks++) {
                const int waA = (8 * ks + 4 * hA) ^ xr7;
                const int waB = (8 * ks + 4 * hB) ^ xr7;
                uint32_t a[4][4];
#pragma unroll
                for (int mi = 0; mi < 4; mi++) {
                    uint32_t ad = xbase + ((wm * 64 + mi * 16) * 32 + arow_off + waA) * 4;
                    LDSM_X4(a[mi][0], a[mi][1], a[mi][2], a[mi][3], ad);
                }
                uint32_t b[4][2];
#pragma unroll
                for (int jp = 0; jp < 2; jp++) {
                    uint32_t bd = wbase + ((wn * 32 + jp * 16) * 32 + brow_off + waB) * 4;
                    LDSM_X4(b[2 * jp][0], b[2 * jp][1], b[2 * jp + 1][0], b[2 * jp + 1][1], bd);
                }
#pragma unroll
                for (int mi = 0; mi < 4; mi++)
#pragma unroll
                    for (int ni = 0; ni < 4; ni++)
                        MMA_F16(acc[mi][ni], a[mi], b[ni]);
            }
        }

        // epilogue: bias, scale, fp16-round; Q/K head-major, V transposed
#pragma unroll
        for (int mi = 0; mi < 4; mi++) {
#pragma unroll
            for (int ni = 0; ni < 4; ni++) {
                int m = m0 + wm * 64 + mi * 16 + lr;
                int n = n0 + wn * 32 + ni * 8 + 2 * lc;
                float b0 = __ldg(&bias[n]), b1 = __ldg(&bias[n + 1]);
                int h = n >> 6, d = n & 63;
#pragma unroll
                for (int half_ = 0; half_ < 2; half_++) {
                    int mm = m + half_ * 8;
                    int b_ = mm >> 11, s_ = mm & 2047;
                    int bh = b_ * HH + h;
                    float v0 = (acc[mi][ni][half_ * 2 + 0] + b0) * oscale;
                    float v1 = (acc[mi][ni][half_ * 2 + 1] + b1) * oscale;
                    if (z == 2) {
                        __half* vt = g_V + ((size_t)bh * DKK + d) * SS + s_;
                        vt[0]  = __float2half_rn(v0);
                        vt[SS] = __float2half_rn(v1);
                    } else {
                        __half* dst = (z == 0) ? g_Q : g_K;
                        __half2 pk = __floats2half2_rn(v0, v1);
                        *(__half2*)&dst[((size_t)bh * SS + s_) * DKK + d] = pk;
                    }
                }
            }
        }
    }
}

// ---------------------------------------------------------------------------
// Causal flash attention, fp16 m16n8k16 + ldmatrix.x4. BM=128, 8 warps.
// Softmax: fp32 sub -> f16x2 pack -> ex2.approx.f16x2 (half the MUFU ops);
// row sums via ones-column MMA (no shfl/fadd reduction). Register P.
// ---------------------------------------------------------------------------
#define AKV 4096   // words per KV stage (K 2048 + V 2048)

__global__ __launch_bounds__(256, 2)
void flash_attn_f16(float* __restrict__ out)
{
    extern __shared__ uint32_t smu[];
    uint32_t* Qs  = smu;                 // 128*32 words
    uint32_t* KV0 = smu + 128 * 32;      // 3 stages x [K 64*32 | V 64*32]

    const int bh = blockIdx.y;
    const int qt = gridDim.x - 1 - blockIdx.x;   // LPT: heavy tiles first
    const int m0 = qt * 128;

    const __half* Qp = g_Q + (size_t)bh * SS * DKK;
    const __half* Kp = g_K + (size_t)bh * SS * DKK;
    const __half* Vp = g_V + (size_t)bh * DKK * SS;   // transposed

    const int tid  = threadIdx.x;
    const int warp = tid >> 5;
    const int lane = tid & 31;
    const int lr = lane >> 2;
    const int lc = lane & 3;
    const int wrow = warp * 16;

    const int l7  = lane & 7;
    const int xr7 = l7 << 2;
    const int hA  = (lane >> 4) & 1;
    const int gA  = (lane >> 3) & 1;
    const int gB  = (lane >> 4) & 1;
    const int hB  = (lane >> 3) & 1;
    const int arow_off = (8 * gA + l7) * 32;
    const int brow_off = (8 * gB + l7) * 32;

    auto fillKV = [&](int t) {
        const int n0 = t * 64;
        uint32_t* Ks = KV0 + (t % 3) * AKV;
        uint32_t* Vs = Ks + 2048;
#pragma unroll
        for (int e = tid; e < 512; e += 256) {
            int r = e >> 3, c4 = e & 7;
            int pos = r * 32 + ((c4 * 4) ^ ((r & 7) << 2));
            cp16(saddr(&Ks[pos]), &Kp[(size_t)(n0 + r) * DKK + c4 * 8]);
            cp16(saddr(&Vs[pos]), &Vp[(size_t)r * SS + n0 + c4 * 8]);
        }
    };

    // prologue: Q group, KV(0), KV(1)
#pragma unroll
    for (int e = tid; e < 1024; e += 256) {
        int r = e >> 3, c4 = e & 7;
        int pos = r * 32 + ((c4 * 4) ^ ((r & 7) << 2));
        cp16(saddr(&Qs[pos]), &Qp[(size_t)(m0 + r) * DKK + c4 * 8]);
    }
    CP_COMMIT();
    fillKV(0); CP_COMMIT();
    const int ntiles = 2 * qt + 2;
    if (1 < ntiles) fillKV(1);
    CP_COMMIT();

    CP_WAIT2();
    __syncthreads();
    uint32_t qa[4][4];
#pragma unroll
    for (int ks = 0; ks < 4; ks++) {
        const int waA = (8 * ks + 4 * hA) ^ xr7;
        uint32_t ad = saddr(Qs) + (wrow * 32 + arow_off + waA) * 4;
        LDSM_X4(qa[ks][0], qa[ks][1], qa[ks][2], qa[ks][3], ad);
    }

    float m_i[2], l_i[2], o[8][4];
    m_i[0] = m_i[1] = -1e30f;
    l_i[0] = l_i[1] = 0.f;
#pragma unroll
    for (int nb = 0; nb < 8; nb++)
#pragma unroll
        for (int c = 0; c < 4; c++) o[nb][c] = 0.f;

    const uint32_t ONESW = 0x3C003C00u;   // (1.0h, 1.0h)
    uint32_t onesb[2] = {ONESW, ONESW};

    for (int t = 0; t < ntiles; t++) {
        const int n0 = t * 64;

        CP_WAIT1();
        __syncthreads();

        if (t + 2 < ntiles) fillKV(t + 2);
        CP_COMMIT();

        const uint32_t kbase = saddr(KV0 + (t % 3) * AKV);
        const uint32_t vbase = kbase + 2048 * 4;

        // S = Q K^T (warp: 16x64)
        float sc[8][4];
#pragma unroll
        for (int nb = 0; nb < 8; nb++)
#pragma unroll
            for (int c = 0; c < 4; c++) sc[nb][c] = 0.f;

#pragma unroll
        for (int ks = 0; ks < 4; ks++) {
            const int waB = (8 * ks + 4 * hB) ^ xr7;
            uint32_t b[8][2];
#pragma unroll
            for (int jp = 0; jp < 4; jp++) {
                uint32_t bd = kbase + ((jp * 16) * 32 + brow_off + waB) * 4;
                LDSM_X4(b[2 * jp][0], b[2 * jp][1], b[2 * jp + 1][0], b[2 * jp + 1][1], bd);
            }
#pragma unroll
            for (int nb = 0; nb < 8; nb++)
                MMA_F16(sc[nb], qa[ks], b[nb]);
        }

        // causal mask (diagonal tiles only)
        if (t >= 2 * qt) {
            const int row0 = m0 + wrow + lr;
            const int row1 = row0 + 8;
#pragma unroll
            for (int nb = 0; nb < 8; nb++) {
                int col = n0 + nb * 8 + 2 * lc;
                if (col > row0)     sc[nb][0] = -1e30f;
                if (col + 1 > row0) sc[nb][1] = -1e30f;
                if (col > row1)     sc[nb][2] = -1e30f;
                if (col + 1 > row1) sc[nb][3] = -1e30f;
            }
        }

        // online softmax: rowmax tree, then f16x2 exp into A-fragments
        float rmax0 = -1e30f, rmax1 = -1e30f;
#pragma unroll
        for (int nb = 0; nb < 8; nb++) {
            rmax0 = fmaxf(rmax0, fmaxf(sc[nb][0], sc[nb][1]));
            rmax1 = fmaxf(rmax1, fmaxf(sc[nb][2], sc[nb][3]));
        }
#pragma unroll
        for (int off = 1; off < 4; off <<= 1) {
            rmax0 = fmaxf(rmax0, __shfl_xor_sync(0xffffffffu, rmax0, off));
            rmax1 = fmaxf(rmax1, __shfl_xor_sync(0xffffffffu, rmax1, off));
        }
        float mnew0 = fmaxf(m_i[0], rmax0);
        float mnew1 = fmaxf(m_i[1], rmax1);
        float corr0 = ex2(m_i[0] - mnew0);
        float corr1 = ex2(m_i[1] - mnew1);
        m_i[0] = mnew0; m_i[1] = mnew1;

        uint32_t plo[8], phi[8];
#pragma unroll
        for (int nb = 0; nb < 8; nb++) {
            plo[nb] = h2ex2(packh2(sc[nb][0] - mnew0, sc[nb][1] - mnew0));
            phi[nb] = h2ex2(packh2(sc[nb][2] - mnew1, sc[nb][3] - mnew1));
        }

        // row sums via ones-MMA (fp32 accumulate; all output cols = rowsum)
        float rs[4] = {0.f, 0.f, 0.f, 0.f};
#pragma unroll
        for (int j = 0; j < 4; j++) {
            uint32_t a[4];
            a[0] = plo[2 * j];
            a[1] = phi[2 * j];
            a[2] = plo[2 * j + 1];
            a[3] = phi[2 * j + 1];
            MMA_F16(rs, a, onesb);
        }
        l_i[0] = l_i[0] * corr0 + rs[0];
        l_i[1] = l_i[1] * corr1 + rs[2];
#pragma unroll
        for (int nb = 0; nb < 8; nb++) {
            o[nb][0] *= corr0; o[nb][1] *= corr0;
            o[nb][2] *= corr1; o[nb][3] *= corr1;
        }

        // O += P V  (A = register P, B = Vt rows)
#pragma unroll
        for (int j = 0; j < 4; j++) {
            uint32_t a[4];
            a[0] = plo[2 * j];
            a[1] = phi[2 * j];
            a[2] = plo[2 * j + 1];
            a[3] = phi[2 * j + 1];
            const int waB = (8 * j + 4 * hB) ^ xr7;
            uint32_t b[8][2];
#pragma unroll
            for (int jp = 0; jp < 4; jp++) {
                uint32_t bd = vbase + ((jp * 16) * 32 + brow_off + waB) * 4;
                LDSM_X4(b[2 * jp][0], b[2 * jp][1], b[2 * jp + 1][0], b[2 * jp + 1][1], bd);
            }
#pragma unroll
            for (int nb = 0; nb < 8; nb++)
                MMA_F16(o[nb], a, b[nb]);
        }
    }

    // epilogue
    const int b = bh >> 4;
    const int h = bh & 15;
    const float inv0 = 1.0f / l_i[0];
    const float inv1 = 1.0f / l_i[1];
    const int row0 = m0 + wrow + lr;
#pragma unroll
    for (int nb = 0; nb < 8; nb++) {
        int d = h * DKK + nb * 8 + 2 * lc;
        float2 v0, v1;
        v0.x = o[nb][0] * inv0; v0.y = o[nb][1] * inv0;
        v1.x = o[nb][2] * inv1; v1.y = o[nb][3] * inv1;
        *(float2*)&out[((size_t)(b * SS + row0)) * DD + d] = v0;
        *(float2*)&out[((size_t)(b * SS + row0 + 8)) * DD + d] = v1;
    }
}

// ---------------------------------------------------------------------------
extern "C" void kernel_launch(void* const* d_in, const int* in_sizes, int n_in,
                              void* d_out, int out_size)
{
    const float* q  = (const float*)d_in[0];
    const float* v  = (const float*)d_in[1];
    const float* k  = (const float*)d_in[2];
    // d_in[3] = attn_mask (causal, known analytically) — unused
    const float* Wq = (const float*)d_in[4];
    const float* bq = (const float*)d_in[5];
    const float* Wk = (const float*)d_in[6];
    const float* bk = (const float*)d_in[7];
    const float* Wv = (const float*)d_in[8];
    const float* bv = (const float*)d_in[9];
    float* out = (float*)d_out;

    cvt_prepass<<<dim3(2048, 6), 256>>>(q, k, v, Wq, Wk, Wv);

    const int gemmSmem = 3 * GSTAGE * sizeof(uint32_t);   // 98304
    cudaFuncSetAttribute(qkv_gemm_f16, cudaFuncAttributeMaxDynamicSharedMemorySize, gemmSmem);
    qkv_gemm_f16<<<296, 256, gemmSmem>>>(bq, bk, bv);

    const int attnSmem = (128 * 32 + 3 * AKV) * sizeof(uint32_t);  // 65536
    cudaFuncSetAttribute(flash_attn_f16, cudaFuncAttributeMaxDynamicSharedMemorySize, attnSmem);
    dim3 gAttn(SS / 128, BB * HH);
    flash_attn_f16<<<gAttn, 256, attnSmem>>>(out);
}